// round 1
// baseline (speedup 1.0000x reference)
#include <cuda_runtime.h>
#include <math.h>

#define BATCH 8
#define NTOK  1024
#define KVD   960
#define NH    4
#define HKV   (NH * KVD)   // 3840

// ---------------- scratch (static __device__ — no allocations allowed) ----------------
static __device__ float g_K[(size_t)BATCH * NH * NTOK * KVD];   // [b,h,n,o]
static __device__ float g_V[(size_t)BATCH * NTOK * HKV];        // [b,n,h*960+o]
static __device__ float g_Q[(size_t)BATCH * NH * NTOK * 512];   // [b,h,n,c] (max branch)
static __device__ float g_S[(size_t)BATCH * 512 * HKV];         // [b,c,h*960+o]
static __device__ float g_CX[(size_t)BATCH * 512 * NTOK];       // [b,c,n]
static __device__ float g_mu[BATCH * NH];
static __device__ float g_rs[BATCH * NH];

// ---------------- generic batched SGEMM: C[m,n] = alpha * sum_k Aval(m,k)*Bval(n,k) ----
// Aval = TA ? A[k*lda+m] : A[m*lda+k];  Bval = TB ? B[k*ldb+n] : B[n*ldb+k]
// per-z operand offset: (z/div)*s1 + (z%div)*s2
template <bool TA, bool TB>
__global__ __launch_bounds__(256) void gemm64(
    const float* __restrict__ Abase, const float* __restrict__ Bbase, float* __restrict__ Cbase,
    int M, int N, int K, int lda, int ldb, int ldc,
    int aDiv, long long aS1, long long aS2,
    int bDiv, long long bS1, long long bS2,
    int cDiv, long long cS1, long long cS2,
    float alpha)
{
    const int z = blockIdx.z;
    const float* A = Abase + (long long)(z / aDiv) * aS1 + (long long)(z % aDiv) * aS2;
    const float* B = Bbase + (long long)(z / bDiv) * bS1 + (long long)(z % bDiv) * bS2;
    float*       C = Cbase + (long long)(z / cDiv) * cS1 + (long long)(z % cDiv) * cS2;

    __shared__ __align__(16) float As[16][68];
    __shared__ __align__(16) float Bs[16][68];

    const int tid = threadIdx.x;
    const int tx = tid & 15;
    const int ty = tid >> 4;
    const int tileM = blockIdx.y * 64;
    const int tileN = blockIdx.x * 64;

    float acc[4][4];
#pragma unroll
    for (int i = 0; i < 4; i++)
#pragma unroll
        for (int j = 0; j < 4; j++) acc[i][j] = 0.f;

    for (int kt = 0; kt < K; kt += 16) {
        if (TA) {
            const int m = tid & 63, k0 = tid >> 6;
#pragma unroll
            for (int i = 0; i < 4; i++) {
                const int k = k0 * 4 + i;
                As[k][m] = A[(long long)(kt + k) * lda + (tileM + m)];
            }
        } else {
            const int k = tid & 15, m0 = tid >> 4;
#pragma unroll
            for (int i = 0; i < 4; i++) {
                const int m = m0 + i * 16;
                As[k][m] = A[(long long)(tileM + m) * lda + (kt + k)];
            }
        }
        if (TB) {
            const int n = tid & 63, k0 = tid >> 6;
#pragma unroll
            for (int i = 0; i < 4; i++) {
                const int k = k0 * 4 + i;
                Bs[k][n] = B[(long long)(kt + k) * ldb + (tileN + n)];
            }
        } else {
            const int k = tid & 15, n0 = tid >> 4;
#pragma unroll
            for (int i = 0; i < 4; i++) {
                const int n = n0 + i * 16;
                Bs[k][n] = B[(long long)(tileN + n) * ldb + (kt + k)];
            }
        }
        __syncthreads();
#pragma unroll
        for (int k = 0; k < 16; k++) {
            const float4 av = *(const float4*)&As[k][ty * 4];
            const float4 bv = *(const float4*)&Bs[k][tx * 4];
            const float a[4] = {av.x, av.y, av.z, av.w};
            const float b[4] = {bv.x, bv.y, bv.z, bv.w};
#pragma unroll
            for (int i = 0; i < 4; i++)
#pragma unroll
                for (int j = 0; j < 4; j++) acc[i][j] += a[i] * b[j];
        }
        __syncthreads();
    }

#pragma unroll
    for (int i = 0; i < 4; i++) {
        float4 v = make_float4(acc[i][0] * alpha, acc[i][1] * alpha,
                               acc[i][2] * alpha, acc[i][3] * alpha);
        *(float4*)&C[(long long)(tileM + ty * 4 + i) * ldc + (tileN + tx * 4)] = v;
    }
}

// ---------------- InstanceNorm stats: mean/var over (C, KV) per (b,h) -------------------
__global__ void meanvar_kernel(const float* __restrict__ S, int C,
                               float* __restrict__ mu, float* __restrict__ rs)
{
    const int z = blockIdx.x;            // b*NH + h
    const int b = z / NH, h = z % NH;
    const float* base = S + (long long)b * C * HKV + (long long)h * KVD;
    float s = 0.f, s2 = 0.f;
    for (int c = 0; c < C; c++) {
        const float* row = base + (long long)c * HKV;
        for (int j = threadIdx.x; j < KVD; j += blockDim.x) {
            const float v = row[j];
            s += v;
            s2 += v * v;
        }
    }
    __shared__ float sa[512], sb[512];
    sa[threadIdx.x] = s;
    sb[threadIdx.x] = s2;
    __syncthreads();
    for (int off = 256; off > 0; off >>= 1) {
        if (threadIdx.x < off) {
            sa[threadIdx.x] += sa[threadIdx.x + off];
            sb[threadIdx.x] += sb[threadIdx.x + off];
        }
        __syncthreads();
    }
    if (threadIdx.x == 0) {
        const float cnt = (float)C * (float)KVD;
        const float m = sa[0] / cnt;
        const float var = sb[0] / cnt - m * m;
        mu[z] = m;
        rs[z] = rsqrtf(var + 1e-5f);
    }
}

// ---------------- fused instance-norm apply + row softmax (in place) --------------------
__global__ __launch_bounds__(256) void norm_softmax_kernel(
    float* __restrict__ S, int C,
    const float* __restrict__ mu, const float* __restrict__ rs)
{
    const int z = blockIdx.x;            // ((b*C)+c)*NH + h
    const int h = z % NH;
    const int bc = z / NH;
    const int c = bc % C;
    const int b = bc / C;
    float* row = S + ((long long)b * C + c) * HKV + (long long)h * KVD;
    const float m = mu[b * NH + h];
    const float r = rs[b * NH + h];

    __shared__ float buf[KVD];
    __shared__ float red[256];

    float lmax = -1e30f;
    for (int j = threadIdx.x; j < KVD; j += 256) {
        const float v = (row[j] - m) * r;
        buf[j] = v;
        lmax = fmaxf(lmax, v);
    }
    red[threadIdx.x] = lmax;
    __syncthreads();
    for (int off = 128; off > 0; off >>= 1) {
        if (threadIdx.x < off) red[threadIdx.x] = fmaxf(red[threadIdx.x], red[threadIdx.x + off]);
        __syncthreads();
    }
    const float gmax = red[0];
    __syncthreads();

    float lsum = 0.f;
    for (int j = threadIdx.x; j < KVD; j += 256) {
        const float e = __expf(buf[j] - gmax);
        buf[j] = e;
        lsum += e;
    }
    red[threadIdx.x] = lsum;
    __syncthreads();
    for (int off = 128; off > 0; off >>= 1) {
        if (threadIdx.x < off) red[threadIdx.x] += red[threadIdx.x + off];
        __syncthreads();
    }
    const float inv = 1.f / red[0];
    for (int j = threadIdx.x; j < KVD; j += 256) row[j] = buf[j] * inv;
}

// ---------------- host launch ------------------------------------------------------------
extern "C" void kernel_launch(void* const* d_in, const int* in_sizes, int n_in,
                              void* d_out, int out_size)
{
    const float* emb[4]  = {(const float*)d_in[0], (const float*)d_in[1],
                            (const float*)d_in[2], (const float*)d_in[3]};
    const float* emb_all = (const float*)d_in[4];
    const float* Wq[4]   = {(const float*)d_in[5], (const float*)d_in[6],
                            (const float*)d_in[7], (const float*)d_in[8]};
    const float* Wk      = (const float*)d_in[9];
    const float* Wv      = (const float*)d_in[10];
    const float* Wo[4]   = {(const float*)d_in[11], (const float*)d_in[12],
                            (const float*)d_in[13], (const float*)d_in[14]};
    float* out = (float*)d_out;

    float *Kp, *Vp, *Qp, *Sp, *Cxp, *mup, *rsp;
    cudaGetSymbolAddress((void**)&Kp,  g_K);
    cudaGetSymbolAddress((void**)&Vp,  g_V);
    cudaGetSymbolAddress((void**)&Qp,  g_Q);
    cudaGetSymbolAddress((void**)&Sp,  g_S);
    cudaGetSymbolAddress((void**)&Cxp, g_CX);
    cudaGetSymbolAddress((void**)&mup, g_mu);
    cudaGetSymbolAddress((void**)&rsp, g_rs);

    const float rscale = 1.f / sqrtf(960.f);

    // K[b,h] = emb_all[b] @ Wk[h]^T  -> g_K [b,h,n,o], ldc=960
    gemm64<false, false><<<dim3(KVD / 64, NTOK / 64, BATCH * NH), 256>>>(
        emb_all, Wk, Kp,
        NTOK, KVD, KVD, KVD, KVD, KVD,
        NH, (long long)NTOK * KVD, 0,
        NH, 0, (long long)KVD * KVD,
        1, (long long)NTOK * KVD, 0, 1.f);

    // V[b,h] = emb_all[b] @ Wv[h]^T  -> g_V [b,n,h*960+o], ldc=3840
    gemm64<false, false><<<dim3(KVD / 64, NTOK / 64, BATCH * NH), 256>>>(
        emb_all, Wv, Vp,
        NTOK, KVD, KVD, KVD, KVD, HKV,
        NH, (long long)NTOK * KVD, 0,
        NH, 0, (long long)KVD * KVD,
        NH, (long long)NTOK * HKV, KVD, 1.f);

    const int dims[4] = {64, 128, 256, 512};
    long long outOff = 0;
    for (int br = 0; br < 4; br++) {
        const int Cb = dims[br];

        // Q[b,h] = emb[b] @ Wq[h]^T -> g_Q [z,n,c]
        gemm64<false, false><<<dim3(Cb / 64, NTOK / 64, BATCH * NH), 256>>>(
            emb[br], Wq[br], Qp,
            NTOK, Cb, Cb, Cb, Cb, Cb,
            NH, (long long)NTOK * Cb, 0,
            NH, 0, (long long)Cb * Cb,
            1, (long long)NTOK * Cb, 0, 1.f);

        // scores[b,h] = Q^T @ K / sqrt(KV) -> g_S [b, c, h*960+o], ldc=3840
        gemm64<true, true><<<dim3(KVD / 64, Cb / 64, BATCH * NH), 256>>>(
            Qp, Kp, Sp,
            Cb, KVD, NTOK, Cb, KVD, HKV,
            1, (long long)NTOK * Cb, 0,
            1, (long long)NTOK * KVD, 0,
            NH, (long long)Cb * HKV, KVD, rscale);

        // InstanceNorm stats per (b,h), then fused norm+softmax per row
        meanvar_kernel<<<BATCH * NH, 512>>>(Sp, Cb, mup, rsp);
        norm_softmax_kernel<<<BATCH * Cb * NH, 256>>>(Sp, Cb, mup, rsp);

        // ctx[b] = (1/H) * probs[b] (C x 3840) @ V[b]^T (3840 x 1024) -> g_CX [b,c,n]
        gemm64<false, false><<<dim3(NTOK / 64, Cb / 64, BATCH), 256>>>(
            Sp, Vp, Cxp,
            Cb, NTOK, HKV, HKV, HKV, NTOK,
            1, (long long)Cb * HKV, 0,
            1, (long long)NTOK * HKV, 0,
            1, (long long)Cb * NTOK, 0, 0.25f);

        // O[b] = ctx[b]^T (N x C) @ Wo^T -> out
        gemm64<true, false><<<dim3(Cb / 64, NTOK / 64, BATCH), 256>>>(
            Cxp, Wo[br], out + outOff,
            NTOK, Cb, Cb, NTOK, Cb, Cb,
            1, (long long)Cb * NTOK, 0,
            1, 0, 0,
            1, (long long)NTOK * Cb, 0, 1.f);

        outOff += (long long)BATCH * NTOK * Cb;
    }
    (void)in_sizes; (void)n_in; (void)out_size;
}

// round 3
// speedup vs baseline: 1.4696x; 1.4696x over previous
#include <cuda_runtime.h>
#include <math.h>

#define BATCH 8
#define NTOK  1024
#define KVD   960
#define NH    4
#define HKV   (NH * KVD)   // 3840

typedef unsigned long long ull;

// ---------------- scratch (static __device__ — no allocations allowed) ----------------
static __device__ float g_G [(size_t)BATCH * 512 * KVD];        // [b][C][960]   emb^T @ emb_all
static __device__ float g_T [(size_t)BATCH * NH * 512 * KVD];   // [b,h][C][960] Wq @ G
static __device__ float g_S [(size_t)BATCH * 512 * HKV];        // [b][C][h*960+o] scores/probs
static __device__ float g_U [(size_t)BATCH * NH * 512 * KVD];   // [b,h][C][960] probs @ Wv
static __device__ float g_Us[(size_t)BATCH * 512 * KVD];        // [b][C][960]   0.25 * sum_h U
static __device__ float g_CX[(size_t)BATCH * 512 * NTOK];       // [b][C][N]
static __device__ float g_mu[BATCH * NH];
static __device__ float g_rs[BATCH * NH];

// ---------------- packed fp32x2 FMA ----------------
__device__ __forceinline__ void ffma2(ull& d, ull a, ull b) {
    asm("fma.rn.f32x2 %0, %1, %2, %0;" : "+l"(d) : "l"(a), "l"(b));
}

// ---------------- batched GEMM: C[m,n] = alpha * sum_k Aval(m,k)*Bval(n,k) --------------
// Aval = TA ? A[k*lda+m] : A[m*lda+k];  Bval = TB ? B[k*ldb+n] : B[n*ldb+k]
// per-z operand offset: (z/div)*s1 + (z%div)*s2
// Tile 128x128x16, 256 threads, double-buffered smem, FFMA2 inner loop.
// A tile stored DUPLICATED as float2(a,a); B tile stored plain; each FFMA2 does 2 n's.
template <bool TA, bool TB>
__global__ __launch_bounds__(256, 2) void gemm128(
    const float* __restrict__ Abase, const float* __restrict__ Bbase, float* __restrict__ Cbase,
    int M, int N, int K, int lda, int ldb, int ldc,
    int aDiv, long long aS1, long long aS2,
    int bDiv, long long bS1, long long bS2,
    int cDiv, long long cS1, long long cS2,
    float alpha)
{
    __shared__ __align__(16) float2 Ad[2][16][128];   // 32 KB
    __shared__ __align__(16) float  Bs[2][16][128];   // 16 KB

    const int z = blockIdx.z;
    const float* A = Abase + (long long)(z / aDiv) * aS1 + (long long)(z % aDiv) * aS2;
    const float* B = Bbase + (long long)(z / bDiv) * bS1 + (long long)(z % bDiv) * bS2;
    float*       C = Cbase + (long long)(z / cDiv) * cS1 + (long long)(z % cDiv) * cS2;

    const int tid = threadIdx.x;
    const int tx = tid & 15;
    const int ty = tid >> 4;
    const int tileM = blockIdx.y * 128;
    const int tileN = blockIdx.x * 128;

    float4 fa0, fa1, fb0, fb1;
    const float4 Z4 = make_float4(0.f, 0.f, 0.f, 0.f);

    auto ldg = [&](int kt) {
        if (TA) {
            const int k = tid >> 4, m0 = (tid & 15) * 8;
            const float* p = A + (long long)(kt + k) * lda + tileM + m0;
            fa0 = (tileM + m0     < M) ? *(const float4*)(p)     : Z4;
            fa1 = (tileM + m0 + 4 < M) ? *(const float4*)(p + 4) : Z4;
        } else {
            const int m = tid >> 1, kh = (tid & 1) * 8;
            const float* p = A + (long long)(tileM + m) * lda + kt + kh;
            const bool v = (tileM + m) < M;
            fa0 = v ? *(const float4*)(p)     : Z4;
            fa1 = v ? *(const float4*)(p + 4) : Z4;
        }
        if (TB) {
            const int k = tid >> 4, n0 = (tid & 15) * 8;
            const float* p = B + (long long)(kt + k) * ldb + tileN + n0;
            fb0 = (tileN + n0     < N) ? *(const float4*)(p)     : Z4;
            fb1 = (tileN + n0 + 4 < N) ? *(const float4*)(p + 4) : Z4;
        } else {
            const int n = tid >> 1, kh = (tid & 1) * 8;
            const float* p = B + (long long)(tileN + n) * ldb + kt + kh;
            const bool v = (tileN + n) < N;
            fb0 = v ? *(const float4*)(p)     : Z4;
            fb1 = v ? *(const float4*)(p + 4) : Z4;
        }
    };

    auto sts = [&](int buf) {
        if (TA) {
            const int k = tid >> 4, m0 = (tid & 15) * 8;
            float2* d = &Ad[buf][k][m0];
            d[0] = make_float2(fa0.x, fa0.x); d[1] = make_float2(fa0.y, fa0.y);
            d[2] = make_float2(fa0.z, fa0.z); d[3] = make_float2(fa0.w, fa0.w);
            d[4] = make_float2(fa1.x, fa1.x); d[5] = make_float2(fa1.y, fa1.y);
            d[6] = make_float2(fa1.z, fa1.z); d[7] = make_float2(fa1.w, fa1.w);
        } else {
            const int m = tid >> 1, kh = (tid & 1) * 8;
            Ad[buf][kh + 0][m] = make_float2(fa0.x, fa0.x);
            Ad[buf][kh + 1][m] = make_float2(fa0.y, fa0.y);
            Ad[buf][kh + 2][m] = make_float2(fa0.z, fa0.z);
            Ad[buf][kh + 3][m] = make_float2(fa0.w, fa0.w);
            Ad[buf][kh + 4][m] = make_float2(fa1.x, fa1.x);
            Ad[buf][kh + 5][m] = make_float2(fa1.y, fa1.y);
            Ad[buf][kh + 6][m] = make_float2(fa1.z, fa1.z);
            Ad[buf][kh + 7][m] = make_float2(fa1.w, fa1.w);
        }
        if (TB) {
            const int k = tid >> 4, n0 = (tid & 15) * 8;
            *(float4*)&Bs[buf][k][n0]     = fb0;
            *(float4*)&Bs[buf][k][n0 + 4] = fb1;
        } else {
            const int n = tid >> 1, kh = (tid & 1) * 8;
            Bs[buf][kh + 0][n] = fb0.x; Bs[buf][kh + 1][n] = fb0.y;
            Bs[buf][kh + 2][n] = fb0.z; Bs[buf][kh + 3][n] = fb0.w;
            Bs[buf][kh + 4][n] = fb1.x; Bs[buf][kh + 5][n] = fb1.y;
            Bs[buf][kh + 6][n] = fb1.z; Bs[buf][kh + 7][n] = fb1.w;
        }
    };

    ull acc[8][4];
#pragma unroll
    for (int i = 0; i < 8; i++)
#pragma unroll
        for (int j = 0; j < 4; j++) acc[i][j] = 0ull;

    auto compute = [&](int buf) {
#pragma unroll
        for (int k = 0; k < 16; k++) {
            const ulonglong2 t0 = *(const ulonglong2*)&Ad[buf][k][ty * 4];
            const ulonglong2 t1 = *(const ulonglong2*)&Ad[buf][k][ty * 4 + 2];
            const ulonglong2 t2 = *(const ulonglong2*)&Ad[buf][k][64 + ty * 4];
            const ulonglong2 t3 = *(const ulonglong2*)&Ad[buf][k][64 + ty * 4 + 2];
            ull a[8] = {t0.x, t0.y, t1.x, t1.y, t2.x, t2.y, t3.x, t3.y};
            const ulonglong2 bb0 = *(const ulonglong2*)&Bs[buf][k][tx * 4];
            const ulonglong2 bb1 = *(const ulonglong2*)&Bs[buf][k][64 + tx * 4];
            ull bp[4] = {bb0.x, bb0.y, bb1.x, bb1.y};
#pragma unroll
            for (int i = 0; i < 8; i++) {
                ffma2(acc[i][0], a[i], bp[0]);
                ffma2(acc[i][1], a[i], bp[1]);
                ffma2(acc[i][2], a[i], bp[2]);
                ffma2(acc[i][3], a[i], bp[3]);
            }
        }
    };

    ldg(0);
    sts(0);
    __syncthreads();
    const int nk = K >> 4;
    int buf = 0;
    for (int it = 1; it < nk; it++) {
        ldg(it * 16);
        compute(buf);
        sts(buf ^ 1);
        __syncthreads();
        buf ^= 1;
    }
    compute(buf);

    // epilogue
    union UF { ull u; float2 f; };
#pragma unroll
    for (int i = 0; i < 8; i++) {
        const int m = tileM + ((i < 4) ? (ty * 4 + i) : (64 + ty * 4 + i - 4));
        if (m >= M) continue;
        UF u0, u1;
        u0.u = acc[i][0]; u1.u = acc[i][1];
        if (tileN + tx * 4 < N) {
            float4 r = make_float4(u0.f.x * alpha, u0.f.y * alpha, u1.f.x * alpha, u1.f.y * alpha);
            *(float4*)&C[(long long)m * ldc + tileN + tx * 4] = r;
        }
        u0.u = acc[i][2]; u1.u = acc[i][3];
        if (tileN + 64 + tx * 4 < N) {
            float4 r = make_float4(u0.f.x * alpha, u0.f.y * alpha, u1.f.x * alpha, u1.f.y * alpha);
            *(float4*)&C[(long long)m * ldc + tileN + 64 + tx * 4] = r;
        }
    }
}

// ---------------- InstanceNorm stats: mean/var over (C, KV) per (b,h) -------------------
__global__ void meanvar_kernel(const float* __restrict__ S, int C,
                               float* __restrict__ mu, float* __restrict__ rs)
{
    const int z = blockIdx.x;            // b*NH + h
    const int b = z / NH, h = z % NH;
    const float* base = S + (long long)b * C * HKV + (long long)h * KVD;
    float s = 0.f, s2 = 0.f;
    for (int c = 0; c < C; c++) {
        const float* row = base + (long long)c * HKV;
        for (int j = threadIdx.x; j < KVD; j += blockDim.x) {
            const float v = row[j];
            s += v;
            s2 += v * v;
        }
    }
    __shared__ float sa[512], sb[512];
    sa[threadIdx.x] = s;
    sb[threadIdx.x] = s2;
    __syncthreads();
    for (int off = 256; off > 0; off >>= 1) {
        if (threadIdx.x < off) {
            sa[threadIdx.x] += sa[threadIdx.x + off];
            sb[threadIdx.x] += sb[threadIdx.x + off];
        }
        __syncthreads();
    }
    if (threadIdx.x == 0) {
        const float cnt = (float)C * (float)KVD;
        const float m = sa[0] / cnt;
        const float var = sb[0] / cnt - m * m;
        mu[z] = m;
        rs[z] = rsqrtf(var + 1e-5f);
    }
}

// ---------------- fused instance-norm apply + row softmax (in place) --------------------
__global__ __launch_bounds__(256) void norm_softmax_kernel(
    float* __restrict__ S, int C,
    const float* __restrict__ mu, const float* __restrict__ rs)
{
    const int z = blockIdx.x;            // ((b*C)+c)*NH + h
    const int h = z % NH;
    const int bc = z / NH;
    const int c = bc % C;
    const int b = bc / C;
    float* row = S + ((long long)b * C + c) * HKV + (long long)h * KVD;
    const float m = mu[b * NH + h];
    const float r = rs[b * NH + h];

    __shared__ float buf[KVD];
    __shared__ float red[256];

    float lmax = -1e30f;
    for (int j = threadIdx.x; j < KVD; j += 256) {
        const float v = (row[j] - m) * r;
        buf[j] = v;
        lmax = fmaxf(lmax, v);
    }
    red[threadIdx.x] = lmax;
    __syncthreads();
    for (int off = 128; off > 0; off >>= 1) {
        if (threadIdx.x < off) red[threadIdx.x] = fmaxf(red[threadIdx.x], red[threadIdx.x + off]);
        __syncthreads();
    }
    const float gmax = red[0];
    __syncthreads();

    float lsum = 0.f;
    for (int j = threadIdx.x; j < KVD; j += 256) {
        const float e = __expf(buf[j] - gmax);
        buf[j] = e;
        lsum += e;
    }
    red[threadIdx.x] = lsum;
    __syncthreads();
    for (int off = 128; off > 0; off >>= 1) {
        if (threadIdx.x < off) red[threadIdx.x] += red[threadIdx.x + off];
        __syncthreads();
    }
    const float inv = 1.f / red[0];
    for (int j = threadIdx.x; j < KVD; j += 256) row[j] = buf[j] * inv;
}

// ---------------- head reduction: Us[b] = 0.25 * sum_h U[b,h] ----------------------------
__global__ void hreduce_kernel(const float* __restrict__ U, float* __restrict__ Us, int per_b)
{
    const long long idx = (long long)blockIdx.x * blockDim.x + threadIdx.x;
    const long long total = (long long)BATCH * per_b;
    if (idx >= total) return;
    const int b = (int)(idx / per_b);
    const long long r = idx % per_b;
    const float* p = U + (long long)b * NH * per_b + r;
    Us[idx] = 0.25f * (p[0] + p[per_b] + p[2LL * per_b] + p[3LL * per_b]);
}

// ---------------- host launch ------------------------------------------------------------
extern "C" void kernel_launch(void* const* d_in, const int* in_sizes, int n_in,
                              void* d_out, int out_size)
{
    const float* emb[4]  = {(const float*)d_in[0], (const float*)d_in[1],
                            (const float*)d_in[2], (const float*)d_in[3]};
    const float* emb_all = (const float*)d_in[4];
    const float* Wq[4]   = {(const float*)d_in[5], (const float*)d_in[6],
                            (const float*)d_in[7], (const float*)d_in[8]};
    const float* Wk      = (const float*)d_in[9];
    const float* Wv      = (const float*)d_in[10];
    const float* Wo[4]   = {(const float*)d_in[11], (const float*)d_in[12],
                            (const float*)d_in[13], (const float*)d_in[14]};
    float* out = (float*)d_out;

    float *Gp, *Tp, *Sp, *Up, *Usp, *CXp, *mup, *rsp;
    cudaGetSymbolAddress((void**)&Gp,  g_G);
    cudaGetSymbolAddress((void**)&Tp,  g_T);
    cudaGetSymbolAddress((void**)&Sp,  g_S);
    cudaGetSymbolAddress((void**)&Up,  g_U);
    cudaGetSymbolAddress((void**)&Usp, g_Us);
    cudaGetSymbolAddress((void**)&CXp, g_CX);
    cudaGetSymbolAddress((void**)&mup, g_mu);
    cudaGetSymbolAddress((void**)&rsp, g_rs);

    const float rscale = 1.f / sqrtf(960.f);
    const int dims[4] = {64, 128, 256, 512};
    long long outOff = 0;

    for (int br = 0; br < 4; br++) {
        const int Cb = dims[br];
        const int gy = (Cb + 127) / 128;

        // G[b] = emb[b]^T @ emb_all[b]   (C x 960, K=1024), z=8
        gemm128<true, true><<<dim3(8, gy, BATCH), 256>>>(
            emb[br], emb_all, Gp,
            Cb, KVD, NTOK, Cb, KVD, KVD,
            1, (long long)NTOK * Cb, 0,
            1, (long long)NTOK * KVD, 0,
            1, (long long)Cb * KVD, 0, 1.f);

        // T[b,h] = Wq[h] @ G[b]          (C x 960, K=C), z=32
        gemm128<false, true><<<dim3(8, gy, BATCH * NH), 256>>>(
            Wq[br], Gp, Tp,
            Cb, KVD, Cb, Cb, KVD, KVD,
            NH, 0, (long long)Cb * Cb,
            NH, (long long)Cb * KVD, 0,
            1, (long long)Cb * KVD, 0, 1.f);

        // scores[b,h] = T[b,h] @ Wk[h]^T / sqrt(KV)  (C x 960, K=960), z=32
        gemm128<false, false><<<dim3(8, gy, BATCH * NH), 256>>>(
            Tp, Wk, Sp,
            Cb, KVD, KVD, KVD, KVD, HKV,
            1, (long long)Cb * KVD, 0,
            NH, 0, (long long)KVD * KVD,
            NH, (long long)Cb * HKV, KVD, rscale);

        // InstanceNorm stats per (b,h), then fused norm+softmax per row
        meanvar_kernel<<<BATCH * NH, 512>>>(Sp, Cb, mup, rsp);
        norm_softmax_kernel<<<BATCH * Cb * NH, 256>>>(Sp, Cb, mup, rsp);

        // U[b,h] = probs[b,h] @ Wv[h]    (C x 960, K=960), z=32
        gemm128<false, true><<<dim3(8, gy, BATCH * NH), 256>>>(
            Sp, Wv, Up,
            Cb, KVD, KVD, HKV, KVD, KVD,
            NH, (long long)Cb * HKV, KVD,
            NH, 0, (long long)KVD * KVD,
            1, (long long)Cb * KVD, 0, 1.f);

        // Us[b] = 0.25 * sum_h U[b,h]   (the ONLY place the head-mean factor lives)
        {
            const int per_b = Cb * KVD;
            const long long total = (long long)BATCH * per_b;
            hreduce_kernel<<<(int)((total + 255) / 256), 256>>>(Up, Usp, per_b);
        }

        // ctx[b] = Us[b] @ emb_all[b]^T  (C x 1024, K=960), z=8  — alpha=1 (0.25 already applied)
        gemm128<false, false><<<dim3(NTOK / 128, gy, BATCH), 256>>>(
            Usp, emb_all, CXp,
            Cb, NTOK, KVD, KVD, KVD, NTOK,
            1, (long long)Cb * KVD, 0,
            1, (long long)NTOK * KVD, 0,
            1, (long long)Cb * NTOK, 0, 1.f);

        // O[b] = ctx[b]^T @ Wo^T         (1024 x C, K=C), z=8
        gemm128<true, false><<<dim3((Cb + 127) / 128, NTOK / 128, BATCH), 256>>>(
            CXp, Wo[br], out + outOff,
            NTOK, Cb, Cb, NTOK, Cb, Cb,
            1, (long long)Cb * NTOK, 0,
            1, 0, 0,
            1, (long long)NTOK * Cb, 0, 1.f);

        outOff += (long long)BATCH * NTOK * Cb;
    }
    (void)in_sizes; (void)n_in; (void)out_size;
}

// round 5
// speedup vs baseline: 2.4484x; 1.6661x over previous
#include <cuda_runtime.h>
#include <cstdint>
#include <math.h>

#define BATCH 8
#define NTOK  1024
#define KVD   960
#define NH    4
#define HKV   (NH * KVD)   // 3840

typedef long long ll;

// ---------------- scratch (static __device__ — no allocations allowed) ----------------
static __device__ float g_G [(size_t)BATCH * 512 * KVD];        // [b][C][960]   emb^T @ emb_all
static __device__ float g_T [(size_t)BATCH * NH * 512 * KVD];   // [b,h][C][960] Wq @ G
static __device__ float g_S [(size_t)BATCH * 512 * HKV];        // [b][C][h*960+o] scores/probs
static __device__ float g_U [(size_t)BATCH * NH * 512 * KVD];   // [b,h][C][960] probs @ Wv
static __device__ float g_Us[(size_t)BATCH * 512 * KVD];        // [b][C][960]   0.25 * sum_h U
static __device__ float g_CX[(size_t)BATCH * 512 * NTOK];       // [b][C][N]
static __device__ float g_mu[BATCH * NH];
static __device__ float g_rs[BATCH * NH];
static __device__ float g_part[BATCH * NH * 16 * 2];

// ---------------- tf32 helpers (sm_80 PTX — compiles on plain compute_103) -------------
__device__ __forceinline__ uint32_t to_tf32(float f) {
    uint32_t r;
    asm("cvt.rna.tf32.f32 %0, %1;" : "=r"(r) : "f"(f));
    return r;
}

__device__ __forceinline__ void mma_tf32(float* c, uint32_t a0, uint32_t a1,
                                         uint32_t a2, uint32_t a3,
                                         uint32_t b0, uint32_t b1) {
    asm volatile(
        "mma.sync.aligned.m16n8k8.row.col.f32.tf32.tf32.f32 "
        "{%0,%1,%2,%3}, {%4,%5,%6,%7}, {%8,%9}, {%0,%1,%2,%3};"
        : "+f"(c[0]), "+f"(c[1]), "+f"(c[2]), "+f"(c[3])
        : "r"(a0), "r"(a1), "r"(a2), "r"(a3), "r"(b0), "r"(b1));
}

// ---- fragment-order smem addressing for a 128(rows) x 32(k) chunk ----
// A chunk: [s(4)][mtile(8)][lane(32)][reg(4)]  -> 4096 floats (16 KB)
// B chunk: [s(4)][ntile(16)][lane(32)][reg(2)] -> 4096 floats (16 KB)
__device__ __forceinline__ int fragA_addr(int m, int k) {
    const int lane = ((m & 7) << 2) | (k & 3);
    const int reg  = ((m >> 3) & 1) | (((k >> 2) & 1) << 1);
    return (((((k >> 3) << 3) + (m >> 4)) << 5 | lane) << 2) + reg;
}
__device__ __forceinline__ int fragB_addr(int n, int k) {
    const int lane = ((n & 7) << 2) | (k & 3);
    const int reg  = (k >> 2) & 1;
    return (((((k >> 3) << 4) + (n >> 3)) << 5 | lane) << 1) + reg;
}

// ---- ldg: 16 floats per thread per operand-chunk ----
template <bool T>
__device__ __forceinline__ void ldg_frag(const float* __restrict__ src, int ld,
                                         int tile, int lim, int kt, int tid, float* v)
{
    if (!T) {               // row-major [row][k]
        const int r = tid >> 1, h = tid & 1;
        const int row = tile + r;
        const bool ok = row < lim;
        const float4* p = (const float4*)(src + (ll)row * ld + kt + h * 16);
        const float4 Z = make_float4(0.f, 0.f, 0.f, 0.f);
        float4 q0 = ok ? p[0] : Z;
        float4 q1 = ok ? p[1] : Z;
        float4 q2 = ok ? p[2] : Z;
        float4 q3 = ok ? p[3] : Z;
        v[0]=q0.x; v[1]=q0.y; v[2]=q0.z; v[3]=q0.w;
        v[4]=q1.x; v[5]=q1.y; v[6]=q1.z; v[7]=q1.w;
        v[8]=q2.x; v[9]=q2.y; v[10]=q2.z; v[11]=q2.w;
        v[12]=q3.x; v[13]=q3.y; v[14]=q3.z; v[15]=q3.w;
    } else {                // k-major [k][row]
        const int wid = tid >> 5, lane = tid & 31;
#pragma unroll
        for (int s4 = 0; s4 < 4; s4++) {
            const int task = wid + 8 * s4;
            const int kq = task & 7, mb = task >> 3;
            const int gm = tile + mb * 32 + lane;
            const bool ok = gm < lim;
            const float* p = src + (ll)(kt + kq * 4) * ld + gm;
#pragma unroll
            for (int i = 0; i < 4; i++)
                v[s4 * 4 + i] = ok ? p[(ll)i * ld] : 0.f;
        }
    }
}

// ---- sts: scatter 16 floats (cvt to tf32) into fragment-order smem ----
template <bool T, bool ISA>
__device__ __forceinline__ void sts_frag(uint32_t* sp, int tid, const float* v)
{
    if (!T) {
        const int r = tid >> 1, h = tid & 1;
#pragma unroll
        for (int idx = 0; idx < 16; idx++) {
            const int k = h * 16 + idx;
            sp[ISA ? fragA_addr(r, k) : fragB_addr(r, k)] = to_tf32(v[idx]);
        }
    } else {
        const int wid = tid >> 5, lane = tid & 31;
#pragma unroll
        for (int s4 = 0; s4 < 4; s4++) {
            const int task = wid + 8 * s4;
            const int kq = task & 7, mb = task >> 3;
            const int m = mb * 32 + lane;
#pragma unroll
            for (int i = 0; i < 4; i++) {
                const int k = kq * 4 + i;
                sp[ISA ? fragA_addr(m, k) : fragB_addr(m, k)] = to_tf32(v[s4 * 4 + i]);
            }
        }
    }
}

// ---------------- dynamic smem layout (bytes) ----------------
#define SM_A0 0
#define SM_A1 16384
#define SM_B0 32768
#define SM_B1 49152
#define SM_TOTAL 65536

// ======================= tensor-core tf32 batched GEMM =======================
// C[m,n] = alpha * sum_k Aval(m,k) * Bval(n,k)
// Aval = TA ? A[k*lda+m] : A[m*lda+k]   (same for B with TB)
// 128x128 tile, 8 warps (4m x 2n), warp tile 32x64, K-chunks of 32, double-buffered.
template <bool TA, bool TB>
__global__ __launch_bounds__(256)
void tgemm(const float* __restrict__ Abase, const float* __restrict__ Bbase,
           float* __restrict__ Cbase,
           int M, int N, int K, int lda, int ldb, int ldc,
           int aDiv, ll aS1, ll aS2,
           int bDiv, ll bS1, ll bS2,
           int cDiv, ll cS1, ll cS2,
           float alpha)
{
    extern __shared__ char smem[];

    const int z = blockIdx.z;
    const float* A = Abase + (ll)(z / aDiv) * aS1 + (ll)(z % aDiv) * aS2;
    const float* B = Bbase + (ll)(z / bDiv) * bS1 + (ll)(z % bDiv) * bS2;
    float*       C = Cbase + (ll)(z / cDiv) * cS1 + (ll)(z % cDiv) * cS2;

    const int tid  = threadIdx.x;
    const int lane = tid & 31;
    const int wid  = tid >> 5;
    const int wm   = wid >> 1;      // 0..3
    const int wn   = wid & 1;       // 0..1
    const int tileM = blockIdx.y * 128;
    const int tileN = blockIdx.x * 128;

    uint32_t* aBuf[2] = {(uint32_t*)(smem + SM_A0), (uint32_t*)(smem + SM_A1)};
    uint32_t* bBuf[2] = {(uint32_t*)(smem + SM_B0), (uint32_t*)(smem + SM_B1)};

    float acc[2][8][4];
#pragma unroll
    for (int i = 0; i < 2; i++)
#pragma unroll
        for (int j = 0; j < 8; j++)
#pragma unroll
            for (int t = 0; t < 4; t++) acc[i][j][t] = 0.f;

    float va[16], vb[16];

    auto compute = [&](int buf) {
        const uint4* ap = (const uint4*)aBuf[buf];
        const uint2* bp = (const uint2*)bBuf[buf];
#pragma unroll
        for (int s = 0; s < 4; s++) {
            uint4 av[2];
#pragma unroll
            for (int i = 0; i < 2; i++)
                av[i] = ap[((s * 8 + wm * 2 + i) << 5) + lane];
            uint2 bv[8];
#pragma unroll
            for (int j = 0; j < 8; j++)
                bv[j] = bp[((s * 16 + wn * 8 + j) << 5) + lane];
#pragma unroll
            for (int i = 0; i < 2; i++)
#pragma unroll
                for (int j = 0; j < 8; j++)
                    mma_tf32(acc[i][j], av[i].x, av[i].y, av[i].z, av[i].w,
                             bv[j].x, bv[j].y);
        }
    };

    const int nk = K >> 5;   // all K are multiples of 32, nk >= 2

    ldg_frag<TA>(A, lda, tileM, M, 0, tid, va);
    ldg_frag<TB>(B, ldb, tileN, N, 0, tid, vb);
    sts_frag<TA, true >(aBuf[0], tid, va);
    sts_frag<TB, false>(bBuf[0], tid, vb);
    __syncthreads();

    int buf = 0;
    for (int it = 1; it < nk; it++) {
        ldg_frag<TA>(A, lda, tileM, M, it * 32, tid, va);
        ldg_frag<TB>(B, ldb, tileN, N, it * 32, tid, vb);
        compute(buf);
        sts_frag<TA, true >(aBuf[buf ^ 1], tid, va);
        sts_frag<TB, false>(bBuf[buf ^ 1], tid, vb);
        __syncthreads();
        buf ^= 1;
    }
    compute(buf);

    // epilogue: d0,d1 -> (row, col..col+1); d2,d3 -> (row+8, col..col+1)
#pragma unroll
    for (int i = 0; i < 2; i++) {
#pragma unroll
        for (int j = 0; j < 8; j++) {
            const int row = tileM + wm * 32 + i * 16 + (lane >> 2);
            const int col = tileN + wn * 64 + j * 8 + ((lane & 3) << 1);
            if (col < N) {
                if (row < M) {
                    float2 v = make_float2(acc[i][j][0] * alpha, acc[i][j][1] * alpha);
                    *(float2*)&C[(ll)row * ldc + col] = v;
                }
                if (row + 8 < M) {
                    float2 v = make_float2(acc[i][j][2] * alpha, acc[i][j][3] * alpha);
                    *(float2*)&C[(ll)(row + 8) * ldc + col] = v;
                }
            }
        }
    }
}

// ---------------- InstanceNorm stats: 2-stage deterministic reduction -------------------
__global__ __launch_bounds__(256) void mv_partial(const float* __restrict__ S, int C,
                                                  float* __restrict__ part)
{
    const int z = blockIdx.x;            // b*NH + h  (32)
    const int slice = blockIdx.y;        // 16 slices
    const int b = z / NH, h = z % NH;
    const int rows = C / 16;
    const float* base = S + (ll)b * C * HKV + (ll)h * KVD + (ll)slice * rows * HKV;
    float s = 0.f, s2 = 0.f;
    for (int r = 0; r < rows; r++) {
        const float* row = base + (ll)r * HKV;
        for (int j = threadIdx.x; j < KVD; j += 256) {
            const float v = row[j];
            s += v;
            s2 += v * v;
        }
    }
    __shared__ float sa[256], sb[256];
    sa[threadIdx.x] = s; sb[threadIdx.x] = s2;
    __syncthreads();
    for (int off = 128; off > 0; off >>= 1) {
        if (threadIdx.x < off) {
            sa[threadIdx.x] += sa[threadIdx.x + off];
            sb[threadIdx.x] += sb[threadIdx.x + off];
        }
        __syncthreads();
    }
    if (threadIdx.x == 0) {
        part[(z * 16 + slice) * 2 + 0] = sa[0];
        part[(z * 16 + slice) * 2 + 1] = sb[0];
    }
}

__global__ void mv_final(const float* __restrict__ part, int C,
                         float* __restrict__ mu, float* __restrict__ rs)
{
    const int z = threadIdx.x;
    if (z >= BATCH * NH) return;
    float s = 0.f, s2 = 0.f;
    for (int i = 0; i < 16; i++) {
        s  += part[(z * 16 + i) * 2 + 0];
        s2 += part[(z * 16 + i) * 2 + 1];
    }
    const float cnt = (float)C * (float)KVD;
    const float m = s / cnt;
    const float var = s2 / cnt - m * m;
    mu[z] = m;
    rs[z] = rsqrtf(var + 1e-5f);
}

// ---------------- fused instance-norm apply + row softmax (in place) --------------------
__global__ __launch_bounds__(256) void norm_softmax_kernel(
    float* __restrict__ S, int C,
    const float* __restrict__ mu, const float* __restrict__ rs)
{
    const int z = blockIdx.x;            // ((b*C)+c)*NH + h
    const int h = z % NH;
    const int bc = z / NH;
    const int c = bc % C;
    const int b = bc / C;
    float* row = S + ((ll)b * C + c) * HKV + (ll)h * KVD;
    const float m = mu[b * NH + h];
    const float r = rs[b * NH + h];

    __shared__ float buf[KVD];
    __shared__ float red[256];

    float lmax = -1e30f;
    for (int j = threadIdx.x; j < KVD; j += 256) {
        const float v = (row[j] - m) * r;
        buf[j] = v;
        lmax = fmaxf(lmax, v);
    }
    red[threadIdx.x] = lmax;
    __syncthreads();
    for (int off = 128; off > 0; off >>= 1) {
        if (threadIdx.x < off) red[threadIdx.x] = fmaxf(red[threadIdx.x], red[threadIdx.x + off]);
        __syncthreads();
    }
    const float gmax = red[0];
    __syncthreads();

    float lsum = 0.f;
    for (int j = threadIdx.x; j < KVD; j += 256) {
        const float e = __expf(buf[j] - gmax);
        buf[j] = e;
        lsum += e;
    }
    red[threadIdx.x] = lsum;
    __syncthreads();
    for (int off = 128; off > 0; off >>= 1) {
        if (threadIdx.x < off) red[threadIdx.x] += red[threadIdx.x + off];
        __syncthreads();
    }
    const float inv = 1.f / red[0];
    for (int j = threadIdx.x; j < KVD; j += 256) row[j] = buf[j] * inv;
}

// ---------------- head reduction: Us[b] = 0.25 * sum_h U[b,h] ----------------------------
__global__ void hreduce_kernel(const float* __restrict__ U, float* __restrict__ Us, int per_b)
{
    const ll idx = (ll)blockIdx.x * blockDim.x + threadIdx.x;
    const ll total = (ll)BATCH * per_b;
    if (idx >= total) return;
    const int b = (int)(idx / per_b);
    const ll r = idx % per_b;
    const float* p = U + (ll)b * NH * per_b + r;
    Us[idx] = 0.25f * (p[0] + p[per_b] + p[2LL * per_b] + p[3LL * per_b]);
}

// ---------------- host launch ------------------------------------------------------------
extern "C" void kernel_launch(void* const* d_in, const int* in_sizes, int n_in,
                              void* d_out, int out_size)
{
    const float* emb[4]  = {(const float*)d_in[0], (const float*)d_in[1],
                            (const float*)d_in[2], (const float*)d_in[3]};
    const float* emb_all = (const float*)d_in[4];
    const float* Wq[4]   = {(const float*)d_in[5], (const float*)d_in[6],
                            (const float*)d_in[7], (const float*)d_in[8]};
    const float* Wk      = (const float*)d_in[9];
    const float* Wv      = (const float*)d_in[10];
    const float* Wo[4]   = {(const float*)d_in[11], (const float*)d_in[12],
                            (const float*)d_in[13], (const float*)d_in[14]};
    float* out = (float*)d_out;

    float *Gp, *Tp, *Sp, *Up, *Usp, *CXp, *mup, *rsp, *partp;
    cudaGetSymbolAddress((void**)&Gp,   g_G);
    cudaGetSymbolAddress((void**)&Tp,   g_T);
    cudaGetSymbolAddress((void**)&Sp,   g_S);
    cudaGetSymbolAddress((void**)&Up,   g_U);
    cudaGetSymbolAddress((void**)&Usp,  g_Us);
    cudaGetSymbolAddress((void**)&CXp,  g_CX);
    cudaGetSymbolAddress((void**)&mup,  g_mu);
    cudaGetSymbolAddress((void**)&rsp,  g_rs);
    cudaGetSymbolAddress((void**)&partp, g_part);

    cudaFuncSetAttribute(tgemm<false, false>, cudaFuncAttributeMaxDynamicSharedMemorySize, SM_TOTAL);
    cudaFuncSetAttribute(tgemm<false, true>,  cudaFuncAttributeMaxDynamicSharedMemorySize, SM_TOTAL);
    cudaFuncSetAttribute(tgemm<true, false>,  cudaFuncAttributeMaxDynamicSharedMemorySize, SM_TOTAL);
    cudaFuncSetAttribute(tgemm<true, true>,   cudaFuncAttributeMaxDynamicSharedMemorySize, SM_TOTAL);

    const float rscale = 1.f / sqrtf(960.f);
    const int dims[4] = {64, 128, 256, 512};
    long long outOff = 0;

    for (int br = 0; br < 4; br++) {
        const int Cb = dims[br];
        const int myt = (Cb + 127) / 128;

        // G[b][c][j] = sum_n emb[b][n][c] * emb_all[b][n][j]   (M=Cb, N=960, K=1024)
        tgemm<true, true><<<dim3(8, myt, BATCH), 256, SM_TOTAL>>>(
            emb[br], emb_all, Gp,
            Cb, KVD, NTOK, Cb, KVD, KVD,
            1, (ll)NTOK * Cb, 0,
            1, (ll)NTOK * KVD, 0,
            1, (ll)Cb * KVD, 0, 1.f);

        // T[b,h][c][j] = sum_d Wq[h][c][d] * G[b][d][j]        (M=Cb, N=960, K=Cb)
        tgemm<false, true><<<dim3(8, myt, BATCH * NH), 256, SM_TOTAL>>>(
            Wq[br], Gp, Tp,
            Cb, KVD, Cb, Cb, KVD, KVD,
            NH, 0, (ll)Cb * Cb,
            NH, (ll)Cb * KVD, 0,
            1, (ll)Cb * KVD, 0, 1.f);

        // scores[b,h][c][o] = sum_k T[b,h][c][k] * Wk[h][o][k] / sqrt(960)
        tgemm<false, false><<<dim3(8, myt, BATCH * NH), 256, SM_TOTAL>>>(
            Tp, Wk, Sp,
            Cb, KVD, KVD, KVD, KVD, HKV,
            1, (ll)Cb * KVD, 0,
            NH, 0, (ll)KVD * KVD,
            NH, (ll)Cb * HKV, KVD, rscale);

        // InstanceNorm stats (2-stage), then fused norm+softmax per row
        mv_partial<<<dim3(BATCH * NH, 16), 256>>>(Sp, Cb, partp);
        mv_final<<<1, 32>>>(partp, Cb, mup, rsp);
        norm_softmax_kernel<<<BATCH * Cb * NH, 256>>>(Sp, Cb, mup, rsp);

        // U[b,h][c][k] = sum_o probs[b,h][c][o] * Wv[h][o][k]  (M=Cb, N=960, K=960)
        tgemm<false, true><<<dim3(8, myt, BATCH * NH), 256, SM_TOTAL>>>(
            Sp, Wv, Up,
            Cb, KVD, KVD, HKV, KVD, KVD,
            NH, (ll)Cb * HKV, KVD,
            NH, 0, (ll)KVD * KVD,
            1, (ll)Cb * KVD, 0, 1.f);

        // Us[b] = 0.25 * sum_h U[b,h]
        {
            const int per_b = Cb * KVD;
            const ll total = (ll)BATCH * per_b;
            hreduce_kernel<<<(int)((total + 255) / 256), 256>>>(Up, Usp, per_b);
        }

        // ctx[b][c][n] = sum_k Us[b][c][k] * emb_all[b][n][k]  (M=Cb, N=1024, K=960)
        tgemm<false, false><<<dim3(NTOK / 128, myt, BATCH), 256, SM_TOTAL>>>(
            Usp, emb_all, CXp,
            Cb, NTOK, KVD, KVD, KVD, NTOK,
            1, (ll)Cb * KVD, 0,
            1, (ll)NTOK * KVD, 0,
            1, (ll)Cb * NTOK, 0, 1.f);

        // O[b][n][j] = sum_c ctx[b][c][n] * Wo[j][c]           (M=1024, N=Cb, K=Cb)
        tgemm<true, false><<<dim3((Cb + 127) / 128, NTOK / 128, BATCH), 256, SM_TOTAL>>>(
            CXp, Wo[br], out + outOff,
            NTOK, Cb, Cb, NTOK, Cb, Cb,
            1, (ll)Cb * NTOK, 0,
            1, 0, 0,
            1, (ll)NTOK * Cb, 0, 1.f);

        outOff += (ll)BATCH * NTOK * Cb;
    }
    (void)in_sizes; (void)n_in; (void)out_size;
}

// round 6
// speedup vs baseline: 3.5280x; 1.4409x over previous
#include <cuda_runtime.h>
#include <cuda_fp16.h>
#include <cstdint>
#include <math.h>

#define BATCH 8
#define NTOK  1024
#define KVD   960
#define NH    4
#define HKV   (NH * KVD)   // 3840

typedef long long ll;

// ---------------- scratch (static __device__ — no allocations allowed) ----------------
static __device__ float g_G [(size_t)BATCH * 512 * KVD];        // [b][C][960]
static __device__ float g_T [(size_t)BATCH * NH * 512 * KVD];   // [b,h][C][960]
static __device__ float g_S [(size_t)BATCH * 512 * HKV];        // [b][C][h*960+o]
static __device__ float g_Us[(size_t)BATCH * 512 * KVD];        // [b][C][960]
static __device__ float g_CX[(size_t)BATCH * 512 * NTOK];       // [b][C][N]
static __device__ float g_mu[BATCH * NH];
static __device__ float g_rs[BATCH * NH];
static __device__ float g_part[BATCH * NH * 16 * 2];

// ---------------- fp16 helpers ----------------
__device__ __forceinline__ uint32_t h2pack(float lo, float hi) {
    uint32_t r;
    asm("cvt.rn.f16x2.f32 %0, %1, %2;" : "=r"(r) : "f"(hi), "f"(lo));
    return r;
}

__device__ __forceinline__ void mma16816(float* c, const uint4& a, const uint2& b) {
    asm volatile(
        "mma.sync.aligned.m16n8k16.row.col.f32.f16.f16.f32 "
        "{%0,%1,%2,%3}, {%4,%5,%6,%7}, {%8,%9}, {%0,%1,%2,%3};"
        : "+f"(c[0]), "+f"(c[1]), "+f"(c[2]), "+f"(c[3])
        : "r"(a.x), "r"(a.y), "r"(a.z), "r"(a.w), "r"(b.x), "r"(b.y));
}

// ======================= producers =======================
// Chunk = 128 rows x 32 k (fp16 in smem, fragment order, XOR-swizzled 16B units).
// A frag space: blocks [kb(2)][mb(8)] x 32 lanes x uint4  (8 KB -> 512 uint4)
// B frag space: blocks [kb(2)][nb(16)] x 16 uint4          (8 KB -> 512 uint4)

// A: thread t covers rows {m0, m0+8}, k in {k0..k0+3} u {k0+8..k0+11}
template <bool T>
__device__ __forceinline__ void ldgA(const float* __restrict__ A, int lda, int tileM,
                                     int M, int kt, int t, float4* q)
{
    const int b = t >> 4, kb = b >> 3, mb = b & 7;
    const int m0 = tileM + mb * 16 + ((t & 15) >> 1);
    const int k0 = kt + kb * 16 + (t & 1) * 4;
    const bool v0 = m0 < M, v1 = (m0 + 8) < M;
    if (!T) {
        const float4 Z = make_float4(0.f, 0.f, 0.f, 0.f);
        q[0] = v0 ? *(const float4*)(A + (ll)m0 * lda + k0)           : Z;  // lo0
        q[1] = v0 ? *(const float4*)(A + (ll)m0 * lda + k0 + 8)       : Z;  // hi0
        q[2] = v1 ? *(const float4*)(A + (ll)(m0 + 8) * lda + k0)     : Z;  // lo1
        q[3] = v1 ? *(const float4*)(A + (ll)(m0 + 8) * lda + k0 + 8) : Z;  // hi1
    } else {
        float* f = (float*)q;
#pragma unroll
        for (int run = 0; run < 2; run++)
#pragma unroll
            for (int i = 0; i < 4; i++) {
                const ll ko = (ll)(k0 + run * 8 + i) * lda;
                f[run * 4 + i]     = v0 ? A[ko + m0]     : 0.f;   // q0=lo0, q1=hi0
                f[8 + run * 4 + i] = v1 ? A[ko + m0 + 8] : 0.f;   // q2=lo1, q3=hi1
            }
    }
}

__device__ __forceinline__ void stsA(uint4* sA, int t, const float4* q)
{
    uint4 v0, v1;
    v0.x = h2pack(q[0].x, q[0].y); v0.y = h2pack(q[2].x, q[2].y);
    v0.z = h2pack(q[1].x, q[1].y); v0.w = h2pack(q[3].x, q[3].y);
    v1.x = h2pack(q[0].z, q[0].w); v1.y = h2pack(q[2].z, q[2].w);
    v1.z = h2pack(q[1].z, q[1].w); v1.w = h2pack(q[3].z, q[3].w);
    const int b = t >> 4;
    const int l0 = (t & 15) * 2, l1 = l0 + 1;
    sA[b * 32 + (l0 ^ ((l0 >> 3) & 1))] = v0;
    sA[b * 32 + (l1 ^ ((l1 >> 3) & 1))] = v1;
}

// B: thread t covers one row n, 16 consecutive k
template <bool T>
__device__ __forceinline__ void ldgB(const float* __restrict__ B, int ldb, int tileN,
                                     int N, int kt, int t, float4* q)
{
    const int b = t >> 3, kb = b >> 4, nb = b & 15;
    const int n = tileN + nb * 8 + (t & 7);
    const int k0 = kt + kb * 16;
    const bool v = n < N;
    if (!T) {
        const float4 Z = make_float4(0.f, 0.f, 0.f, 0.f);
        const float4* p = (const float4*)(B + (ll)n * ldb + k0);
        q[0] = v ? p[0] : Z; q[1] = v ? p[1] : Z;
        q[2] = v ? p[2] : Z; q[3] = v ? p[3] : Z;
    } else {
        float* f = (float*)q;
#pragma unroll
        for (int i = 0; i < 16; i++)
            f[i] = v ? B[(ll)(k0 + i) * ldb + n] : 0.f;
    }
}

__device__ __forceinline__ void stsB(uint4* sB, int t, const float4* q)
{
    uint4 v0, v1;
    v0.x = h2pack(q[0].x, q[0].y); v0.y = h2pack(q[2].x, q[2].y);
    v0.z = h2pack(q[0].z, q[0].w); v0.w = h2pack(q[2].z, q[2].w);
    v1.x = h2pack(q[1].x, q[1].y); v1.y = h2pack(q[3].x, q[3].y);
    v1.z = h2pack(q[1].z, q[1].w); v1.w = h2pack(q[3].z, q[3].w);
    const int b = t >> 3;
    const int u0 = (t & 7) * 2, u1 = u0 + 1;
    sB[b * 16 + (u0 ^ ((u0 >> 3) & 1))] = v0;
    sB[b * 16 + (u1 ^ ((u1 >> 3) & 1))] = v1;
}

// ======================= fp16 tensor-core batched GEMM =======================
// C[m,n] = alpha * sum_k Aval(m,k) * Bval(n,k)
// Aval = TA ? A[k*lda+m] : A[m*lda+k]   (same for B with TB)
// 128x128 tile, 8 warps (4m x 2n), K-chunks of 32, double-buffered.
template <bool TA, bool TB>
__global__ __launch_bounds__(256, 2)
void tgemm(const float* __restrict__ Abase, const float* __restrict__ Bbase,
           float* __restrict__ Cbase,
           int M, int N, int K, int lda, int ldb, int ldc,
           int aDiv, ll aS1, ll aS2,
           int bDiv, ll bS1, ll bS2,
           int cDiv, ll cS1, ll cS2,
           float alpha)
{
    __shared__ uint4 sA[2][512];
    __shared__ uint4 sB[2][512];

    const int z = blockIdx.z;
    const float* A = Abase + (ll)(z / aDiv) * aS1 + (ll)(z % aDiv) * aS2;
    const float* B = Bbase + (ll)(z / bDiv) * bS1 + (ll)(z % bDiv) * bS2;
    float*       C = Cbase + (ll)(z / cDiv) * cS1 + (ll)(z % cDiv) * cS2;

    const int tid  = threadIdx.x;
    const int lane = tid & 31;
    const int wid  = tid >> 5;
    const int wm   = wid >> 1;      // 0..3
    const int wn   = wid & 1;       // 0..1
    const int tileM = blockIdx.y * 128;
    const int tileN = blockIdx.x * 128;

    float acc[2][8][4];
#pragma unroll
    for (int i = 0; i < 2; i++)
#pragma unroll
        for (int j = 0; j < 8; j++)
#pragma unroll
            for (int t = 0; t < 4; t++) acc[i][j][t] = 0.f;

    const int la  = lane ^ ((lane >> 3) & 1);                       // A uint4 unit swizzle
    const int lb2 = (((lane >> 1) ^ ((lane >> 4) & 1)) << 1) | (lane & 1);  // B uint2 idx

    auto compute = [&](int buf) {
        const uint4* ap = sA[buf];
        const uint2* bp = (const uint2*)sB[buf];
#pragma unroll
        for (int s = 0; s < 2; s++) {
            uint4 av[2];
#pragma unroll
            for (int i = 0; i < 2; i++)
                av[i] = ap[(s * 8 + wm * 2 + i) * 32 + la];
            uint2 bv[8];
#pragma unroll
            for (int j = 0; j < 8; j++)
                bv[j] = bp[(s * 16 + wn * 8 + j) * 32 + lb2];
#pragma unroll
            for (int i = 0; i < 2; i++)
#pragma unroll
                for (int j = 0; j < 8; j++)
                    mma16816(acc[i][j], av[i], bv[j]);
        }
    };

    const int nk = K >> 5;
    float4 qa[4], qb[4];

    ldgA<TA>(A, lda, tileM, M, 0, tid, qa);
    ldgB<TB>(B, ldb, tileN, N, 0, tid, qb);
    stsA(sA[0], tid, qa);
    stsB(sB[0], tid, qb);
    __syncthreads();

    int buf = 0;
    for (int it = 1; it < nk; it++) {
        ldgA<TA>(A, lda, tileM, M, it * 32, tid, qa);
        ldgB<TB>(B, ldb, tileN, N, it * 32, tid, qb);
        compute(buf);
        stsA(sA[buf ^ 1], tid, qa);
        stsB(sB[buf ^ 1], tid, qb);
        __syncthreads();
        buf ^= 1;
    }
    compute(buf);

    // epilogue
#pragma unroll
    for (int i = 0; i < 2; i++) {
#pragma unroll
        for (int j = 0; j < 8; j++) {
            const int row = tileM + wm * 32 + i * 16 + (lane >> 2);
            const int col = tileN + wn * 64 + j * 8 + ((lane & 3) << 1);
            if (col < N) {
                if (row < M) {
                    float2 v = make_float2(acc[i][j][0] * alpha, acc[i][j][1] * alpha);
                    *(float2*)&C[(ll)row * ldc + col] = v;
                }
                if (row + 8 < M) {
                    float2 v = make_float2(acc[i][j][2] * alpha, acc[i][j][3] * alpha);
                    *(float2*)&C[(ll)(row + 8) * ldc + col] = v;
                }
            }
        }
    }
}

// ---------------- InstanceNorm stats: 2-stage deterministic reduction -------------------
__global__ __launch_bounds__(256) void mv_partial(const float* __restrict__ S, int C,
                                                  float* __restrict__ part)
{
    const int z = blockIdx.x;            // b*NH + h
    const int slice = blockIdx.y;        // 16 slices
    const int b = z / NH, h = z % NH;
    const int rows = C / 16;
    const float* base = S + (ll)b * C * HKV + (ll)h * KVD + (ll)slice * rows * HKV;
    float s = 0.f, s2 = 0.f;
    for (int r = 0; r < rows; r++) {
        const float* row = base + (ll)r * HKV;
        for (int j = threadIdx.x; j < KVD; j += 256) {
            const float v = row[j];
            s += v;
            s2 += v * v;
        }
    }
    __shared__ float sa[256], sb[256];
    sa[threadIdx.x] = s; sb[threadIdx.x] = s2;
    __syncthreads();
    for (int off = 128; off > 0; off >>= 1) {
        if (threadIdx.x < off) {
            sa[threadIdx.x] += sa[threadIdx.x + off];
            sb[threadIdx.x] += sb[threadIdx.x + off];
        }
        __syncthreads();
    }
    if (threadIdx.x == 0) {
        part[(z * 16 + slice) * 2 + 0] = sa[0];
        part[(z * 16 + slice) * 2 + 1] = sb[0];
    }
}

__global__ void mv_final(const float* __restrict__ part, int C,
                         float* __restrict__ mu, float* __restrict__ rs)
{
    const int z = threadIdx.x;
    if (z >= BATCH * NH) return;
    float s = 0.f, s2 = 0.f;
    for (int i = 0; i < 16; i++) {
        s  += part[(z * 16 + i) * 2 + 0];
        s2 += part[(z * 16 + i) * 2 + 1];
    }
    const float cnt = (float)C * (float)KVD;
    const float m = s / cnt;
    const float var = s2 / cnt - m * m;
    mu[z] = m;
    rs[z] = rsqrtf(var + 1e-5f);
}

// ---------------- fused instance-norm apply + row softmax (in place) --------------------
__global__ __launch_bounds__(256) void norm_softmax_kernel(
    float* __restrict__ S, int C,
    const float* __restrict__ mu, const float* __restrict__ rs)
{
    const int z = blockIdx.x;            // ((b*C)+c)*NH + h
    const int h = z % NH;
    const int bc = z / NH;
    const int c = bc % C;
    const int b = bc / C;
    float* row = S + ((ll)b * C + c) * HKV + (ll)h * KVD;
    const float m = mu[b * NH + h];
    const float r = rs[b * NH + h];

    __shared__ float buf[KVD];
    __shared__ float red[256];

    float lmax = -1e30f;
    for (int j = threadIdx.x; j < KVD; j += 256) {
        const float v = (row[j] - m) * r;
        buf[j] = v;
        lmax = fmaxf(lmax, v);
    }
    red[threadIdx.x] = lmax;
    __syncthreads();
    for (int off = 128; off > 0; off >>= 1) {
        if (threadIdx.x < off) red[threadIdx.x] = fmaxf(red[threadIdx.x], red[threadIdx.x + off]);
        __syncthreads();
    }
    const float gmax = red[0];
    __syncthreads();

    float lsum = 0.f;
    for (int j = threadIdx.x; j < KVD; j += 256) {
        const float e = __expf(buf[j] - gmax);
        buf[j] = e;
        lsum += e;
    }
    red[threadIdx.x] = lsum;
    __syncthreads();
    for (int off = 128; off > 0; off >>= 1) {
        if (threadIdx.x < off) red[threadIdx.x] += red[threadIdx.x + off];
        __syncthreads();
    }
    const float inv = 1.f / red[0];
    for (int j = threadIdx.x; j < KVD; j += 256) row[j] = buf[j] * inv;
}

// ---------------- host launch ------------------------------------------------------------
extern "C" void kernel_launch(void* const* d_in, const int* in_sizes, int n_in,
                              void* d_out, int out_size)
{
    const float* emb[4]  = {(const float*)d_in[0], (const float*)d_in[1],
                            (const float*)d_in[2], (const float*)d_in[3]};
    const float* emb_all = (const float*)d_in[4];
    const float* Wq[4]   = {(const float*)d_in[5], (const float*)d_in[6],
                            (const float*)d_in[7], (const float*)d_in[8]};
    const float* Wk      = (const float*)d_in[9];
    const float* Wv      = (const float*)d_in[10];
    const float* Wo[4]   = {(const float*)d_in[11], (const float*)d_in[12],
                            (const float*)d_in[13], (const float*)d_in[14]};
    float* out = (float*)d_out;

    float *Gp, *Tp, *Sp, *Usp, *CXp, *mup, *rsp, *partp;
    cudaGetSymbolAddress((void**)&Gp,   g_G);
    cudaGetSymbolAddress((void**)&Tp,   g_T);
    cudaGetSymbolAddress((void**)&Sp,   g_S);
    cudaGetSymbolAddress((void**)&Usp,  g_Us);
    cudaGetSymbolAddress((void**)&CXp,  g_CX);
    cudaGetSymbolAddress((void**)&mup,  g_mu);
    cudaGetSymbolAddress((void**)&rsp,  g_rs);
    cudaGetSymbolAddress((void**)&partp, g_part);

    const float rscale = 1.f / sqrtf(960.f);
    const int dims[4] = {64, 128, 256, 512};
    long long outOff = 0;

    for (int br = 0; br < 4; br++) {
        const int Cb = dims[br];
        const int myt = (Cb + 127) / 128;

        // G[b][c][j] = sum_n emb[b][n][c] * emb_all[b][n][j]   (M=Cb, N=960, K=1024)
        tgemm<true, true><<<dim3(8, myt, BATCH), 256>>>(
            emb[br], emb_all, Gp,
            Cb, KVD, NTOK, Cb, KVD, KVD,
            1, (ll)NTOK * Cb, 0,
            1, (ll)NTOK * KVD, 0,
            1, (ll)Cb * KVD, 0, 1.f);

        // T[b,h][c][j] = sum_d Wq[h][c][d] * G[b][d][j]        (M=Cb, N=960, K=Cb)
        tgemm<false, true><<<dim3(8, myt, BATCH * NH), 256>>>(
            Wq[br], Gp, Tp,
            Cb, KVD, Cb, Cb, KVD, KVD,
            NH, 0, (ll)Cb * Cb,
            NH, (ll)Cb * KVD, 0,
            1, (ll)Cb * KVD, 0, 1.f);

        // scores[b,h][c][o] = sum_k T[b,h][c][k] * Wk[h][o][k] / sqrt(960)
        tgemm<false, false><<<dim3(8, myt, BATCH * NH), 256>>>(
            Tp, Wk, Sp,
            Cb, KVD, KVD, KVD, KVD, HKV,
            1, (ll)Cb * KVD, 0,
            NH, 0, (ll)KVD * KVD,
            NH, (ll)Cb * HKV, KVD, rscale);

        // InstanceNorm stats (2-stage), then fused norm+softmax per row
        mv_partial<<<dim3(BATCH * NH, 16), 256>>>(Sp, Cb, partp);
        mv_final<<<1, 32>>>(partp, Cb, mup, rsp);
        norm_softmax_kernel<<<BATCH * Cb * NH, 256>>>(Sp, Cb, mup, rsp);

        // Us[b][c][k] = 0.25 * sum_{ho} probs[b][c][ho] * Wv_flat[ho][k]
        // (head-sum folded into ONE GEMM: M=Cb, N=960, K=3840; Wv [h][o][k] flat = [3840][960])
        tgemm<false, true><<<dim3(8, myt, BATCH), 256>>>(
            Sp, Wv, Usp,
            Cb, KVD, HKV, HKV, KVD, KVD,
            1, (ll)Cb * HKV, 0,
            1, 0, 0,
            1, (ll)Cb * KVD, 0, 0.25f);

        // ctx[b][c][n] = sum_k Us[b][c][k] * emb_all[b][n][k]  (M=Cb, N=1024, K=960)
        tgemm<false, false><<<dim3(NTOK / 128, myt, BATCH), 256>>>(
            Usp, emb_all, CXp,
            Cb, NTOK, KVD, KVD, KVD, NTOK,
            1, (ll)Cb * KVD, 0,
            1, (ll)NTOK * KVD, 0,
            1, (ll)Cb * NTOK, 0, 1.f);

        // O[b][n][j] = sum_c ctx[b][c][n] * Wo[j][c]           (M=1024, N=Cb, K=Cb)
        tgemm<true, false><<<dim3((Cb + 127) / 128, NTOK / 128, BATCH), 256>>>(
            CXp, Wo[br], out + outOff,
            NTOK, Cb, Cb, NTOK, Cb, Cb,
            1, (ll)Cb * NTOK, 0,
            1, 0, 0,
            1, (ll)NTOK * Cb, 0, 1.f);

        outOff += (ll)BATCH * NTOK * Cb;
    }
    (void)in_sizes; (void)n_in; (void)out_size;
}

// round 7
// speedup vs baseline: 5.3670x; 1.5213x over previous
#include <cuda_runtime.h>
#include <cuda_fp16.h>
#include <cstdint>
#include <math.h>

#define BATCH 8
#define NTOK  1024
#define KVD   960
#define NH    4
#define HKV   (NH * KVD)   // 3840
#define CT    960          // sum of branch channels 64+128+256+512

typedef long long ll;

// branch constants: C = 64<<br ; channel prefix P = (64<<br)-64
#define BR_C(br)   (64 << (br))
#define BR_P(br)   ((64 << (br)) - 64)

// ---------------- scratch (static __device__ — no allocations allowed) ----------------
static __device__ float g_G [(size_t)BATCH * CT * KVD];          // slab per branch
static __device__ float g_T [(size_t)BATCH * NH * CT * KVD];
static __device__ float g_S [(size_t)BATCH * CT * HKV];
static __device__ float g_Us[(size_t)BATCH * CT * KVD];
static __device__ float g_CX[(size_t)BATCH * CT * NTOK];
static __device__ float g_mu[4 * BATCH * NH];
static __device__ float g_rs[4 * BATCH * NH];
static __device__ float g_part[4 * BATCH * NH * 16 * 2];

// ---------------- fp16 helpers ----------------
__device__ __forceinline__ uint32_t h2pack(float lo, float hi) {
    uint32_t r;
    asm("cvt.rn.f16x2.f32 %0, %1, %2;" : "=r"(r) : "f"(hi), "f"(lo));
    return r;
}

__device__ __forceinline__ void mma16816(float* c, const uint4& a, const uint2& b) {
    asm volatile(
        "mma.sync.aligned.m16n8k16.row.col.f32.f16.f16.f32 "
        "{%0,%1,%2,%3}, {%4,%5,%6,%7}, {%8,%9}, {%0,%1,%2,%3};"
        : "+f"(c[0]), "+f"(c[1]), "+f"(c[2]), "+f"(c[3])
        : "r"(a.x), "r"(a.y), "r"(a.z), "r"(a.w), "r"(b.x), "r"(b.y));
}

// ======================= producers (identical to proven round-6 code) =======================
template <bool T>
__device__ __forceinline__ void ldgA(const float* __restrict__ A, int lda, int tileM,
                                     int M, int kt, int t, float4* q)
{
    const int b = t >> 4, kb = b >> 3, mb = b & 7;
    const int m0 = tileM + mb * 16 + ((t & 15) >> 1);
    const int k0 = kt + kb * 16 + (t & 1) * 4;
    const bool v0 = m0 < M, v1 = (m0 + 8) < M;
    if (!T) {
        const float4 Z = make_float4(0.f, 0.f, 0.f, 0.f);
        q[0] = v0 ? *(const float4*)(A + (ll)m0 * lda + k0)           : Z;
        q[1] = v0 ? *(const float4*)(A + (ll)m0 * lda + k0 + 8)       : Z;
        q[2] = v1 ? *(const float4*)(A + (ll)(m0 + 8) * lda + k0)     : Z;
        q[3] = v1 ? *(const float4*)(A + (ll)(m0 + 8) * lda + k0 + 8) : Z;
    } else {
        float* f = (float*)q;
#pragma unroll
        for (int run = 0; run < 2; run++)
#pragma unroll
            for (int i = 0; i < 4; i++) {
                const ll ko = (ll)(k0 + run * 8 + i) * lda;
                f[run * 4 + i]     = v0 ? A[ko + m0]     : 0.f;
                f[8 + run * 4 + i] = v1 ? A[ko + m0 + 8] : 0.f;
            }
    }
}

__device__ __forceinline__ void stsA(uint4* sA, int t, const float4* q)
{
    uint4 v0, v1;
    v0.x = h2pack(q[0].x, q[0].y); v0.y = h2pack(q[2].x, q[2].y);
    v0.z = h2pack(q[1].x, q[1].y); v0.w = h2pack(q[3].x, q[3].y);
    v1.x = h2pack(q[0].z, q[0].w); v1.y = h2pack(q[2].z, q[2].w);
    v1.z = h2pack(q[1].z, q[1].w); v1.w = h2pack(q[3].z, q[3].w);
    const int b = t >> 4;
    const int l0 = (t & 15) * 2, l1 = l0 + 1;
    sA[b * 32 + (l0 ^ ((l0 >> 3) & 1))] = v0;
    sA[b * 32 + (l1 ^ ((l1 >> 3) & 1))] = v1;
}

template <bool T>
__device__ __forceinline__ void ldgB(const float* __restrict__ B, int ldb, int tileN,
                                     int N, int kt, int t, float4* q)
{
    const int b = t >> 3, kb = b >> 4, nb = b & 15;
    const int n = tileN + nb * 8 + (t & 7);
    const int k0 = kt + kb * 16;
    const bool v = n < N;
    if (!T) {
        const float4 Z = make_float4(0.f, 0.f, 0.f, 0.f);
        const float4* p = (const float4*)(B + (ll)n * ldb + k0);
        q[0] = v ? p[0] : Z; q[1] = v ? p[1] : Z;
        q[2] = v ? p[2] : Z; q[3] = v ? p[3] : Z;
    } else {
        float* f = (float*)q;
#pragma unroll
        for (int i = 0; i < 16; i++)
            f[i] = v ? B[(ll)(k0 + i) * ldb + n] : 0.f;
    }
}

__device__ __forceinline__ void stsB(uint4* sB, int t, const float4* q)
{
    uint4 v0, v1;
    v0.x = h2pack(q[0].x, q[0].y); v0.y = h2pack(q[2].x, q[2].y);
    v0.z = h2pack(q[0].z, q[0].w); v0.w = h2pack(q[2].z, q[2].w);
    v1.x = h2pack(q[1].x, q[1].y); v1.y = h2pack(q[3].x, q[3].y);
    v1.z = h2pack(q[1].z, q[1].w); v1.w = h2pack(q[3].z, q[3].w);
    const int b = t >> 3;
    const int u0 = (t & 7) * 2, u1 = u0 + 1;
    sB[b * 16 + (u0 ^ ((u0 >> 3) & 1))] = v0;
    sB[b * 16 + (u1 ^ ((u1 >> 3) & 1))] = v1;
}

// ======================= merged-stage GEMM descriptors =======================
struct GemmDesc {
    const float* A;
    const float* B;
    float*       C;
    int M, N, K, lda, ldb, ldc;
    int aDiv, bDiv, cDiv;
    ll aS1, aS2, bS1, bS2, cS1, cS2;
    float alpha;
    int xB, yB;     // grid decomposition (z = remainder)
    int off;        // starting global block id
};
struct Desc4 { GemmDesc d[4]; };

// ======================= fp16 tensor-core merged batched GEMM =======================
// One launch covers all 4 branch GEMMs of a stage; block decodes its branch + (x,y,z).
template <bool TA, bool TB>
__global__ __launch_bounds__(256, 2)
void tgemm_m(Desc4 ds)
{
    __shared__ uint4 sA[2][512];
    __shared__ uint4 sB[2][512];

    const int bid = blockIdx.x;
    int br = 0;
    if (bid >= ds.d[1].off) br = 1;
    if (bid >= ds.d[2].off) br = 2;
    if (bid >= ds.d[3].off) br = 3;
    const GemmDesc& g = ds.d[br];

    const int local = bid - g.off;
    const int x  = local % g.xB;
    const int t2 = local / g.xB;
    const int y  = t2 % g.yB;
    const int z  = t2 / g.yB;

    const float* A = g.A + (ll)(z / g.aDiv) * g.aS1 + (ll)(z % g.aDiv) * g.aS2;
    const float* B = g.B + (ll)(z / g.bDiv) * g.bS1 + (ll)(z % g.bDiv) * g.bS2;
    float*       C = g.C + (ll)(z / g.cDiv) * g.cS1 + (ll)(z % g.cDiv) * g.cS2;
    const int M = g.M, N = g.N, K = g.K;
    const int lda = g.lda, ldb = g.ldb, ldc = g.ldc;
    const float alpha = g.alpha;

    const int tid  = threadIdx.x;
    const int lane = tid & 31;
    const int wid  = tid >> 5;
    const int wm   = wid >> 1;
    const int wn   = wid & 1;
    const int tileM = y * 128;
    const int tileN = x * 128;

    float acc[2][8][4];
#pragma unroll
    for (int i = 0; i < 2; i++)
#pragma unroll
        for (int j = 0; j < 8; j++)
#pragma unroll
            for (int t = 0; t < 4; t++) acc[i][j][t] = 0.f;

    const int la  = lane ^ ((lane >> 3) & 1);
    const int lb2 = (((lane >> 1) ^ ((lane >> 4) & 1)) << 1) | (lane & 1);

    auto compute = [&](int buf) {
        const uint4* ap = sA[buf];
        const uint2* bp = (const uint2*)sB[buf];
#pragma unroll
        for (int s = 0; s < 2; s++) {
            uint4 av[2];
#pragma unroll
            for (int i = 0; i < 2; i++)
                av[i] = ap[(s * 8 + wm * 2 + i) * 32 + la];
            uint2 bv[8];
#pragma unroll
            for (int j = 0; j < 8; j++)
                bv[j] = bp[(s * 16 + wn * 8 + j) * 32 + lb2];
#pragma unroll
            for (int i = 0; i < 2; i++)
#pragma unroll
                for (int j = 0; j < 8; j++)
                    mma16816(acc[i][j], av[i], bv[j]);
        }
    };

    const int nk = K >> 5;
    float4 qa[4], qb[4];

    ldgA<TA>(A, lda, tileM, M, 0, tid, qa);
    ldgB<TB>(B, ldb, tileN, N, 0, tid, qb);
    stsA(sA[0], tid, qa);
    stsB(sB[0], tid, qb);
    __syncthreads();

    int buf = 0;
    for (int it = 1; it < nk; it++) {
        ldgA<TA>(A, lda, tileM, M, it * 32, tid, qa);
        ldgB<TB>(B, ldb, tileN, N, it * 32, tid, qb);
        compute(buf);
        stsA(sA[buf ^ 1], tid, qa);
        stsB(sB[buf ^ 1], tid, qb);
        __syncthreads();
        buf ^= 1;
    }
    compute(buf);

#pragma unroll
    for (int i = 0; i < 2; i++) {
#pragma unroll
        for (int j = 0; j < 8; j++) {
            const int row = tileM + wm * 32 + i * 16 + (lane >> 2);
            const int col = tileN + wn * 64 + j * 8 + ((lane & 3) << 1);
            if (col < N) {
                if (row < M) {
                    float2 v = make_float2(acc[i][j][0] * alpha, acc[i][j][1] * alpha);
                    *(float2*)&C[(ll)row * ldc + col] = v;
                }
                if (row + 8 < M) {
                    float2 v = make_float2(acc[i][j][2] * alpha, acc[i][j][3] * alpha);
                    *(float2*)&C[(ll)(row + 8) * ldc + col] = v;
                }
            }
        }
    }
}

// ---------------- merged InstanceNorm stats: partial (all branches) ----------------------
__global__ __launch_bounds__(256) void mv_partial_m(const float* __restrict__ S,
                                                    float* __restrict__ part)
{
    const int bx = blockIdx.x;           // [0, 128): br*32 + (b*NH+h)
    const int br = bx >> 5, z = bx & 31;
    const int slice = blockIdx.y;        // 16 slices
    const int C = BR_C(br);
    const int b = z / NH, h = z % NH;
    const int rows = C / 16;
    const float* base = S + (ll)BATCH * BR_P(br) * HKV
                          + (ll)b * C * HKV + (ll)h * KVD + (ll)slice * rows * HKV;
    float s = 0.f, s2 = 0.f;
    for (int r = 0; r < rows; r++) {
        const float* row = base + (ll)r * HKV;
        for (int j = threadIdx.x; j < KVD; j += 256) {
            const float v = row[j];
            s += v;
            s2 += v * v;
        }
    }
    __shared__ float sa[256], sb[256];
    sa[threadIdx.x] = s; sb[threadIdx.x] = s2;
    __syncthreads();
    for (int off = 128; off > 0; off >>= 1) {
        if (threadIdx.x < off) {
            sa[threadIdx.x] += sa[threadIdx.x + off];
            sb[threadIdx.x] += sb[threadIdx.x + off];
        }
        __syncthreads();
    }
    if (threadIdx.x == 0) {
        part[(bx * 16 + slice) * 2 + 0] = sa[0];
        part[(bx * 16 + slice) * 2 + 1] = sb[0];
    }
}

__global__ void mv_final_m(const float* __restrict__ part,
                           float* __restrict__ mu, float* __restrict__ rs)
{
    const int t = threadIdx.x;           // [0, 128): br*32 + z
    if (t >= 128) return;
    const int br = t >> 5;
    const int C = BR_C(br);
    float s = 0.f, s2 = 0.f;
    for (int i = 0; i < 16; i++) {
        s  += part[(t * 16 + i) * 2 + 0];
        s2 += part[(t * 16 + i) * 2 + 1];
    }
    const float cnt = (float)C * (float)KVD;
    const float m = s / cnt;
    const float var = s2 / cnt - m * m;
    mu[t] = m;
    rs[t] = rsqrtf(var + 1e-5f);
}

// ---------------- merged fused instance-norm apply + row softmax (in place) ---------------
__global__ __launch_bounds__(256) void norm_softmax_m(
    float* __restrict__ S, const float* __restrict__ mu, const float* __restrict__ rs)
{
    // global row id over all branches; per-branch block count = 32*C = 2048<<br
    const int gid = blockIdx.x;
    int br = 0;
    if (gid >= 2048)  br = 1;
    if (gid >= 6144)  br = 2;
    if (gid >= 14336) br = 3;
    const int off = (2048 << br) - 2048;         // 0,2048,6144,14336
    const int local = gid - off;
    const int C = BR_C(br);

    const int h = local % NH;
    const int bc = local / NH;
    const int c = bc % C;
    const int b = bc / C;
    float* row = S + (ll)BATCH * BR_P(br) * HKV
                   + ((ll)b * C + c) * HKV + (ll)h * KVD;
    const float m = mu[br * 32 + b * NH + h];
    const float r = rs[br * 32 + b * NH + h];

    __shared__ float buf[KVD];
    __shared__ float red[256];

    float lmax = -1e30f;
    for (int j = threadIdx.x; j < KVD; j += 256) {
        const float v = (row[j] - m) * r;
        buf[j] = v;
        lmax = fmaxf(lmax, v);
    }
    red[threadIdx.x] = lmax;
    __syncthreads();
    for (int off2 = 128; off2 > 0; off2 >>= 1) {
        if (threadIdx.x < off2) red[threadIdx.x] = fmaxf(red[threadIdx.x], red[threadIdx.x + off2]);
        __syncthreads();
    }
    const float gmax = red[0];
    __syncthreads();

    float lsum = 0.f;
    for (int j = threadIdx.x; j < KVD; j += 256) {
        const float e = __expf(buf[j] - gmax);
        buf[j] = e;
        lsum += e;
    }
    red[threadIdx.x] = lsum;
    __syncthreads();
    for (int off2 = 128; off2 > 0; off2 >>= 1) {
        if (threadIdx.x < off2) red[threadIdx.x] += red[threadIdx.x + off2];
        __syncthreads();
    }
    const float inv = 1.f / red[0];
    for (int j = threadIdx.x; j < KVD; j += 256) row[j] = buf[j] * inv;
}

// ---------------- host launch ------------------------------------------------------------
extern "C" void kernel_launch(void* const* d_in, const int* in_sizes, int n_in,
                              void* d_out, int out_size)
{
    const float* emb[4]  = {(const float*)d_in[0], (const float*)d_in[1],
                            (const float*)d_in[2], (const float*)d_in[3]};
    const float* emb_all = (const float*)d_in[4];
    const float* Wq[4]   = {(const float*)d_in[5], (const float*)d_in[6],
                            (const float*)d_in[7], (const float*)d_in[8]};
    const float* Wk      = (const float*)d_in[9];
    const float* Wv      = (const float*)d_in[10];
    const float* Wo[4]   = {(const float*)d_in[11], (const float*)d_in[12],
                            (const float*)d_in[13], (const float*)d_in[14]};
    float* out = (float*)d_out;

    float *Gp, *Tp, *Sp, *Usp, *CXp, *mup, *rsp, *partp;
    cudaGetSymbolAddress((void**)&Gp,   g_G);
    cudaGetSymbolAddress((void**)&Tp,   g_T);
    cudaGetSymbolAddress((void**)&Sp,   g_S);
    cudaGetSymbolAddress((void**)&Usp,  g_Us);
    cudaGetSymbolAddress((void**)&CXp,  g_CX);
    cudaGetSymbolAddress((void**)&mup,  g_mu);
    cudaGetSymbolAddress((void**)&rsp,  g_rs);
    cudaGetSymbolAddress((void**)&partp, g_part);

    const float rscale = 1.f / sqrtf(960.f);

    // per-branch slab base pointers
    float *Gb[4], *Tb[4], *Sb[4], *Usb[4], *CXb[4], *Ob[4];
    int Cb_[4], myt_[4];
    for (int br = 0; br < 4; br++) {
        const int Cb = BR_C(br), P = BR_P(br);
        Cb_[br] = Cb;
        myt_[br] = (Cb + 127) / 128;
        Gb[br]  = Gp  + (ll)BATCH * P * KVD;
        Tb[br]  = Tp  + (ll)BATCH * NH * P * KVD;
        Sb[br]  = Sp  + (ll)BATCH * P * HKV;
        Usb[br] = Usp + (ll)BATCH * P * KVD;
        CXb[br] = CXp + (ll)BATCH * P * NTOK;
        Ob[br]  = out + (ll)BATCH * NTOK * P;
    }

    auto fill = [](GemmDesc& g, const float* A, const float* B, float* C,
                   int M, int N, int K, int lda, int ldb, int ldc,
                   int aDiv, ll aS1, ll aS2, int bDiv, ll bS1, ll bS2,
                   int cDiv, ll cS1, ll cS2, float alpha,
                   int xB, int yB, int zB, int& cum) {
        g.A = A; g.B = B; g.C = C;
        g.M = M; g.N = N; g.K = K; g.lda = lda; g.ldb = ldb; g.ldc = ldc;
        g.aDiv = aDiv; g.aS1 = aS1; g.aS2 = aS2;
        g.bDiv = bDiv; g.bS1 = bS1; g.bS2 = bS2;
        g.cDiv = cDiv; g.cS1 = cS1; g.cS2 = cS2;
        g.alpha = alpha; g.xB = xB; g.yB = yB; g.off = cum;
        cum += xB * yB * zB;
    };

    Desc4 dG, dT, dS, dU, dCX, dO;
    int nG = 0, nT = 0, nS = 0, nU = 0, nCX = 0, nO = 0;
    for (int br = 0; br < 4; br++) {
        const int Cb = Cb_[br], myt = myt_[br];

        // G[b][c][j] = sum_n emb[b][n][c] * emb_all[b][n][j]   (TA=T, TB=T)
        fill(dG.d[br], emb[br], emb_all, Gb[br],
             Cb, KVD, NTOK, Cb, KVD, KVD,
             1, (ll)NTOK * Cb, 0,  1, (ll)NTOK * KVD, 0,
             1, (ll)Cb * KVD, 0, 1.f, 8, myt, BATCH, nG);

        // T[b,h][c][j] = sum_d Wq[h][c][d] * G[b][d][j]        (TA=N, TB=T)
        fill(dT.d[br], Wq[br], Gb[br], Tb[br],
             Cb, KVD, Cb, Cb, KVD, KVD,
             NH, 0, (ll)Cb * Cb,  NH, (ll)Cb * KVD, 0,
             1, (ll)Cb * KVD, 0, 1.f, 8, myt, BATCH * NH, nT);

        // scores[b,h][c][o] = sum_k T[b,h][c][k] * Wk[h][o][k] (TA=N, TB=N)
        fill(dS.d[br], Tb[br], Wk, Sb[br],
             Cb, KVD, KVD, KVD, KVD, HKV,
             1, (ll)Cb * KVD, 0,  NH, 0, (ll)KVD * KVD,
             NH, (ll)Cb * HKV, KVD, rscale, 8, myt, BATCH * NH, nS);

        // Us[b][c][k] = 0.25 * sum_{ho} probs[b][c][ho] * Wv_flat[ho][k]  (TA=N, TB=T)
        fill(dU.d[br], Sb[br], Wv, Usb[br],
             Cb, KVD, HKV, HKV, KVD, KVD,
             1, (ll)Cb * HKV, 0,  1, 0, 0,
             1, (ll)Cb * KVD, 0, 0.25f, 8, myt, BATCH, nU);

        // ctx[b][c][n] = sum_k Us[b][c][k] * emb_all[b][n][k]  (TA=N, TB=N)
        fill(dCX.d[br], Usb[br], emb_all, CXb[br],
             Cb, NTOK, KVD, KVD, KVD, NTOK,
             1, (ll)Cb * KVD, 0,  1, (ll)NTOK * KVD, 0,
             1, (ll)Cb * NTOK, 0, 1.f, NTOK / 128, myt, BATCH, nCX);

        // O[b][n][j] = sum_c ctx[b][c][n] * Wo[j][c]           (TA=T, TB=N)
        fill(dO.d[br], CXb[br], Wo[br], Ob[br],
             NTOK, Cb, Cb, NTOK, Cb, Cb,
             1, (ll)Cb * NTOK, 0,  1, 0, 0,
             1, (ll)NTOK * Cb, 0, 1.f, myt, NTOK / 128, BATCH, nO);
    }

    // 9 launches total, each stage merged across all branches
    tgemm_m<true,  true ><<<nG,  256>>>(dG);
    tgemm_m<false, true ><<<nT,  256>>>(dT);
    tgemm_m<false, false><<<nS,  256>>>(dS);
    mv_partial_m<<<dim3(128, 16), 256>>>(Sp, partp);
    mv_final_m<<<1, 128>>>(partp, mup, rsp);
    norm_softmax_m<<<30720, 256>>>(Sp, mup, rsp);
    tgemm_m<false, true ><<<nU,  256>>>(dU);
    tgemm_m<false, false><<<nCX, 256>>>(dCX);
    tgemm_m<true,  false><<<nO,  256>>>(dO);

    (void)in_sizes; (void)n_in; (void)out_size;
}

// round 8
// speedup vs baseline: 6.1191x; 1.1401x over previous
#include <cuda_runtime.h>
#include <cuda_fp16.h>
#include <cstdint>
#include <math.h>

#define BATCH 8
#define NTOK  1024
#define KVD   960
#define NH    4
#define HKV   (NH * KVD)   // 3840
#define CT    960          // sum of branch channels 64+128+256+512

typedef long long ll;

#define BR_C(br)   (64 << (br))
#define BR_P(br)   ((64 << (br)) - 64)

// ---------------- scratch (static __device__ — no allocations allowed) ----------------
static __device__ float  g_G  [(size_t)BATCH * CT * KVD];
static __device__ float  g_T  [(size_t)BATCH * NH * CT * KVD];
static __device__ float  g_S  [(size_t)BATCH * CT * HKV];      // fp32 scores
static __device__ __half g_S16[(size_t)BATCH * CT * HKV];      // fp16 probs
static __device__ float  g_Us [(size_t)BATCH * CT * KVD];
static __device__ float  g_CX [(size_t)BATCH * CT * NTOK];
static __device__ float  g_mu [4 * BATCH * NH];
static __device__ float  g_rs [4 * BATCH * NH];
static __device__ float  g_part[2048 * 2];                     // per-tile (sum, sumsq)

// ---------------- fp16 helpers ----------------
__device__ __forceinline__ uint32_t h2pack(float lo, float hi) {
    uint32_t r;
    asm("cvt.rn.f16x2.f32 %0, %1, %2;" : "=r"(r) : "f"(hi), "f"(lo));
    return r;
}

__device__ __forceinline__ void mma16816(float* c, const uint4& a, const uint2& b) {
    asm volatile(
        "mma.sync.aligned.m16n8k16.row.col.f32.f16.f16.f32 "
        "{%0,%1,%2,%3}, {%4,%5,%6,%7}, {%8,%9}, {%0,%1,%2,%3};"
        : "+f"(c[0]), "+f"(c[1]), "+f"(c[2]), "+f"(c[3])
        : "r"(a.x), "r"(a.y), "r"(a.z), "r"(a.w), "r"(b.x), "r"(b.y));
}

// ======================= producers =======================
template <bool T>
__device__ __forceinline__ void ldgA(const float* __restrict__ A, int lda, int tileM,
                                     int M, int kt, int t, float4* q)
{
    const int b = t >> 4, kb = b >> 3, mb = b & 7;
    const int m0 = tileM + mb * 16 + ((t & 15) >> 1);
    const int k0 = kt + kb * 16 + (t & 1) * 4;
    const bool v0 = m0 < M, v1 = (m0 + 8) < M;
    if (!T) {
        const float4 Z = make_float4(0.f, 0.f, 0.f, 0.f);
        q[0] = v0 ? *(const float4*)(A + (ll)m0 * lda + k0)           : Z;
        q[1] = v0 ? *(const float4*)(A + (ll)m0 * lda + k0 + 8)       : Z;
        q[2] = v1 ? *(const float4*)(A + (ll)(m0 + 8) * lda + k0)     : Z;
        q[3] = v1 ? *(const float4*)(A + (ll)(m0 + 8) * lda + k0 + 8) : Z;
    } else {
        float* f = (float*)q;
#pragma unroll
        for (int run = 0; run < 2; run++)
#pragma unroll
            for (int i = 0; i < 4; i++) {
                const ll ko = (ll)(k0 + run * 8 + i) * lda;
                f[run * 4 + i]     = v0 ? A[ko + m0]     : 0.f;
                f[8 + run * 4 + i] = v1 ? A[ko + m0 + 8] : 0.f;
            }
    }
}

__device__ __forceinline__ void stsA(uint4* sA, int t, const float4* q)
{
    uint4 v0, v1;
    v0.x = h2pack(q[0].x, q[0].y); v0.y = h2pack(q[2].x, q[2].y);
    v0.z = h2pack(q[1].x, q[1].y); v0.w = h2pack(q[3].x, q[3].y);
    v1.x = h2pack(q[0].z, q[0].w); v1.y = h2pack(q[2].z, q[2].w);
    v1.z = h2pack(q[1].z, q[1].w); v1.w = h2pack(q[3].z, q[3].w);
    const int b = t >> 4;
    const int l0 = (t & 15) * 2, l1 = l0 + 1;
    sA[b * 32 + (l0 ^ ((l0 >> 3) & 1))] = v0;
    sA[b * 32 + (l1 ^ ((l1 >> 3) & 1))] = v1;
}

// fp16 A (row-major only): 4 x uint2 loads, pure repack, no conversion
__device__ __forceinline__ void ldgA16(const __half* __restrict__ A, int lda, int tileM,
                                       int M, int kt, int t, uint2* w)
{
    const int b = t >> 4, kb = b >> 3, mb = b & 7;
    const int m0 = tileM + mb * 16 + ((t & 15) >> 1);
    const int k0 = kt + kb * 16 + (t & 1) * 4;
    const bool v0 = m0 < M, v1 = (m0 + 8) < M;
    const uint2 Z = make_uint2(0u, 0u);
    w[0] = v0 ? *(const uint2*)(A + (ll)m0 * lda + k0)           : Z;   // lo0
    w[1] = v0 ? *(const uint2*)(A + (ll)m0 * lda + k0 + 8)       : Z;   // hi0
    w[2] = v1 ? *(const uint2*)(A + (ll)(m0 + 8) * lda + k0)     : Z;   // lo1
    w[3] = v1 ? *(const uint2*)(A + (ll)(m0 + 8) * lda + k0 + 8) : Z;   // hi1
}

__device__ __forceinline__ void stsA16(uint4* sA, int t, const uint2* w)
{
    uint4 v0, v1;
    v0.x = w[0].x; v0.y = w[2].x; v0.z = w[1].x; v0.w = w[3].x;
    v1.x = w[0].y; v1.y = w[2].y; v1.z = w[1].y; v1.w = w[3].y;
    const int b = t >> 4;
    const int l0 = (t & 15) * 2, l1 = l0 + 1;
    sA[b * 32 + (l0 ^ ((l0 >> 3) & 1))] = v0;
    sA[b * 32 + (l1 ^ ((l1 >> 3) & 1))] = v1;
}

template <bool T>
__device__ __forceinline__ void ldgB(const float* __restrict__ B, int ldb, int tileN,
                                     int N, int kt, int t, float4* q)
{
    const int b = t >> 3, kb = b >> 4, nb = b & 15;
    const int n = tileN + nb * 8 + (t & 7);
    const int k0 = kt + kb * 16;
    const bool v = n < N;
    if (!T) {
        const float4 Z = make_float4(0.f, 0.f, 0.f, 0.f);
        const float4* p = (const float4*)(B + (ll)n * ldb + k0);
        q[0] = v ? p[0] : Z; q[1] = v ? p[1] : Z;
        q[2] = v ? p[2] : Z; q[3] = v ? p[3] : Z;
    } else {
        float* f = (float*)q;
#pragma unroll
        for (int i = 0; i < 16; i++)
            f[i] = v ? B[(ll)(k0 + i) * ldb + n] : 0.f;
    }
}

__device__ __forceinline__ void stsB(uint4* sB, int t, const float4* q)
{
    uint4 v0, v1;
    v0.x = h2pack(q[0].x, q[0].y); v0.y = h2pack(q[2].x, q[2].y);
    v0.z = h2pack(q[0].z, q[0].w); v0.w = h2pack(q[2].z, q[2].w);
    v1.x = h2pack(q[1].x, q[1].y); v1.y = h2pack(q[3].x, q[3].y);
    v1.z = h2pack(q[1].z, q[1].w); v1.w = h2pack(q[3].z, q[3].w);
    const int b = t >> 3;
    const int u0 = (t & 7) * 2, u1 = u0 + 1;
    sB[b * 16 + (u0 ^ ((u0 >> 3) & 1))] = v0;
    sB[b * 16 + (u1 ^ ((u1 >> 3) & 1))] = v1;
}

// ======================= merged-stage GEMM descriptors =======================
struct GemmDesc {
    const float* A;
    const float* B;
    float*       C;
    int M, N, K, lda, ldb, ldc;
    int aDiv, bDiv, cDiv;
    ll aS1, aS2, bS1, bS2, cS1, cS2;
    float alpha;
    int xB, yB;
    int off;
};
struct Desc4 { GemmDesc d[4]; float* part; };

// ======================= fp16 tensor-core merged batched GEMM =======================
// AH: A operand is fp16 row-major (TA must be false). STATS: epilogue tile (sum,sumsq).
template <bool TA, bool TB, bool STATS, bool AH>
__global__ __launch_bounds__(256, 2)
void tgemm_m(Desc4 ds)
{
    __shared__ uint4 sA[2][512];
    __shared__ uint4 sB[2][512];

    const int bid = blockIdx.x;
    int br = 0;
    if (bid >= ds.d[1].off) br = 1;
    if (bid >= ds.d[2].off) br = 2;
    if (bid >= ds.d[3].off) br = 3;
    const GemmDesc& g = ds.d[br];

    const int local = bid - g.off;
    const int x  = local % g.xB;
    const int t2 = local / g.xB;
    const int y  = t2 % g.yB;
    const int z  = t2 / g.yB;

    const float* A = g.A + (ll)(z / g.aDiv) * g.aS1 + (ll)(z % g.aDiv) * g.aS2;
    const __half* A16 = (const __half*)g.A + (ll)(z / g.aDiv) * g.aS1 + (ll)(z % g.aDiv) * g.aS2;
    const float* B = g.B + (ll)(z / g.bDiv) * g.bS1 + (ll)(z % g.bDiv) * g.bS2;
    float*       C = g.C + (ll)(z / g.cDiv) * g.cS1 + (ll)(z % g.cDiv) * g.cS2;
    const int M = g.M, N = g.N, K = g.K;
    const int lda = g.lda, ldb = g.ldb, ldc = g.ldc;
    const float alpha = g.alpha;

    const int tid  = threadIdx.x;
    const int lane = tid & 31;
    const int wid  = tid >> 5;
    const int wm   = wid >> 1;
    const int wn   = wid & 1;
    const int tileM = y * 128;
    const int tileN = x * 128;

    float acc[2][8][4];
#pragma unroll
    for (int i = 0; i < 2; i++)
#pragma unroll
        for (int j = 0; j < 8; j++)
#pragma unroll
            for (int t = 0; t < 4; t++) acc[i][j][t] = 0.f;

    const int la  = lane ^ ((lane >> 3) & 1);
    const int lb2 = (((lane >> 1) ^ ((lane >> 4) & 1)) << 1) | (lane & 1);

    auto compute = [&](int buf) {
        const uint4* ap = sA[buf];
        const uint2* bp = (const uint2*)sB[buf];
#pragma unroll
        for (int s = 0; s < 2; s++) {
            uint4 av[2];
#pragma unroll
            for (int i = 0; i < 2; i++)
                av[i] = ap[(s * 8 + wm * 2 + i) * 32 + la];
            uint2 bv[8];
#pragma unroll
            for (int j = 0; j < 8; j++)
                bv[j] = bp[(s * 16 + wn * 8 + j) * 32 + lb2];
#pragma unroll
            for (int i = 0; i < 2; i++)
#pragma unroll
                for (int j = 0; j < 8; j++)
                    mma16816(acc[i][j], av[i], bv[j]);
        }
    };

    const int nk = K >> 5;
    float4 qa[4], qb[4];
    uint2  wa[4];

    if (AH) ldgA16(A16, lda, tileM, M, 0, tid, wa);
    else    ldgA<TA>(A, lda, tileM, M, 0, tid, qa);
    ldgB<TB>(B, ldb, tileN, N, 0, tid, qb);
    if (AH) stsA16(sA[0], tid, wa); else stsA(sA[0], tid, qa);
    stsB(sB[0], tid, qb);
    __syncthreads();

    int buf = 0;
    for (int it = 1; it < nk; it++) {
        if (AH) ldgA16(A16, lda, tileM, M, it * 32, tid, wa);
        else    ldgA<TA>(A, lda, tileM, M, it * 32, tid, qa);
        ldgB<TB>(B, ldb, tileN, N, it * 32, tid, qb);
        compute(buf);
        if (AH) stsA16(sA[buf ^ 1], tid, wa); else stsA(sA[buf ^ 1], tid, qa);
        stsB(sB[buf ^ 1], tid, qb);
        __syncthreads();
        buf ^= 1;
    }
    compute(buf);

    if (STATS) {
        // tile (sum, sumsq) of alpha-scaled accumulators; padded entries are exactly 0
        float s = 0.f, s2 = 0.f;
#pragma unroll
        for (int i = 0; i < 2; i++)
#pragma unroll
            for (int j = 0; j < 8; j++)
#pragma unroll
                for (int t = 0; t < 4; t++) {
                    const float v = acc[i][j][t] * alpha;
                    s += v;
                    s2 += v * v;
                }
        __syncthreads();                       // smem reuse safe
        float* sa = (float*)&sA[0][0];
        float* sb = sa + 256;
        sa[tid] = s; sb[tid] = s2;
        __syncthreads();
        for (int off = 128; off > 0; off >>= 1) {
            if (tid < off) { sa[tid] += sa[tid + off]; sb[tid] += sb[tid + off]; }
            __syncthreads();
        }
        if (tid == 0) {
            ds.part[bid * 2 + 0] = sa[0];
            ds.part[bid * 2 + 1] = sb[0];
        }
    }

#pragma unroll
    for (int i = 0; i < 2; i++) {
#pragma unroll
        for (int j = 0; j < 8; j++) {
            const int row = tileM + wm * 32 + i * 16 + (lane >> 2);
            const int col = tileN + wn * 64 + j * 8 + ((lane & 3) << 1);
            if (col < N) {
                if (row < M) {
                    float2 v = make_float2(acc[i][j][0] * alpha, acc[i][j][1] * alpha);
                    *(float2*)&C[(ll)row * ldc + col] = v;
                }
                if (row + 8 < M) {
                    float2 v = make_float2(acc[i][j][2] * alpha, acc[i][j][3] * alpha);
                    *(float2*)&C[(ll)(row + 8) * ldc + col] = v;
                }
            }
        }
    }
}

// ---------------- final stats: fold per-tile partials -> mu, rs ---------------------------
__global__ void mv_final_m(const float* __restrict__ part,
                           float* __restrict__ mu, float* __restrict__ rs)
{
    const int t = threadIdx.x;           // [0, 128): br*32 + z
    if (t >= 128) return;
    const int br = t >> 5, z = t & 31;
    const int offs[4] = {0, 256, 512, 1024};       // dS block offsets per branch
    const int cnt[4]  = {8, 8, 16, 32};            // tiles per (b,h) = 8 * myt
    const int base = offs[br] + z * cnt[br];
    float s = 0.f, s2 = 0.f;
    for (int i = 0; i < cnt[br]; i++) {
        s  += part[(base + i) * 2 + 0];
        s2 += part[(base + i) * 2 + 1];
    }
    const float cntf = (float)BR_C(br) * (float)KVD;
    const float m = s / cntf;
    const float var = s2 / cntf - m * m;
    mu[t] = m;
    rs[t] = rsqrtf(var + 1e-5f);
}

// ---------------- fused norm + softmax: fp32 scores -> fp16 probs, one streaming pass -----
__global__ __launch_bounds__(256) void norm_softmax_m(
    const float* __restrict__ S, __half* __restrict__ S16,
    const float* __restrict__ mu, const float* __restrict__ rs)
{
    const int gid = blockIdx.x;
    int br = 0;
    if (gid >= 2048)  br = 1;
    if (gid >= 6144)  br = 2;
    if (gid >= 14336) br = 3;
    const int off = (2048 << br) - 2048;
    const int local = gid - off;
    const int C = BR_C(br);

    const int h = local % NH;
    const int bc = local / NH;
    const int c = bc % C;
    const int b = bc / C;
    const ll eoff = (ll)BATCH * BR_P(br) * HKV + ((ll)b * C + c) * HKV + (ll)h * KVD;
    const float4* row4  = (const float4*)(S + eoff);
    uint2*        row16 = (uint2*)(S16 + eoff);
    const float m = mu[br * 32 + b * NH + h];
    const float r = rs[br * 32 + b * NH + h];

    const int tid = threadIdx.x;
    float4 e = make_float4(0.f, 0.f, 0.f, 0.f);
    float lsum = 0.f;
    if (tid < 240) {                     // 960 floats = 240 float4
        const float4 v = row4[tid];
        e.x = __expf((v.x - m) * r);
        e.y = __expf((v.y - m) * r);
        e.z = __expf((v.z - m) * r);
        e.w = __expf((v.w - m) * r);
        lsum = (e.x + e.y) + (e.z + e.w);
    }
    __shared__ float red[256];
    red[tid] = lsum;
    __syncthreads();
    for (int o = 128; o > 0; o >>= 1) {
        if (tid < o) red[tid] += red[tid + o];
        __syncthreads();
    }
    const float inv = 1.f / red[0];
    if (tid < 240) {
        uint2 o16;
        o16.x = h2pack(e.x * inv, e.y * inv);
        o16.y = h2pack(e.z * inv, e.w * inv);
        row16[tid] = o16;
    }
}

// ---------------- host launch ------------------------------------------------------------
extern "C" void kernel_launch(void* const* d_in, const int* in_sizes, int n_in,
                              void* d_out, int out_size)
{
    const float* emb[4]  = {(const float*)d_in[0], (const float*)d_in[1],
                            (const float*)d_in[2], (const float*)d_in[3]};
    const float* emb_all = (const float*)d_in[4];
    const float* Wq[4]   = {(const float*)d_in[5], (const float*)d_in[6],
                            (const float*)d_in[7], (const float*)d_in[8]};
    const float* Wk      = (const float*)d_in[9];
    const float* Wv      = (const float*)d_in[10];
    const float* Wo[4]   = {(const float*)d_in[11], (const float*)d_in[12],
                            (const float*)d_in[13], (const float*)d_in[14]};
    float* out = (float*)d_out;

    float *Gp, *Tp, *Sp, *Usp, *CXp, *mup, *rsp, *partp;
    __half* S16p;
    cudaGetSymbolAddress((void**)&Gp,    g_G);
    cudaGetSymbolAddress((void**)&Tp,    g_T);
    cudaGetSymbolAddress((void**)&Sp,    g_S);
    cudaGetSymbolAddress((void**)&S16p,  g_S16);
    cudaGetSymbolAddress((void**)&Usp,   g_Us);
    cudaGetSymbolAddress((void**)&CXp,   g_CX);
    cudaGetSymbolAddress((void**)&mup,   g_mu);
    cudaGetSymbolAddress((void**)&rsp,   g_rs);
    cudaGetSymbolAddress((void**)&partp, g_part);

    const float rscale = 1.f / sqrtf(960.f);

    float *Gb[4], *Tb[4], *Sb[4], *Usb[4], *CXb[4], *Ob[4];
    __half* S16b[4];
    int Cb_[4], myt_[4];
    for (int br = 0; br < 4; br++) {
        const int Cb = BR_C(br), P = BR_P(br);
        Cb_[br] = Cb;
        myt_[br] = (Cb + 127) / 128;
        Gb[br]   = Gp   + (ll)BATCH * P * KVD;
        Tb[br]   = Tp   + (ll)BATCH * NH * P * KVD;
        Sb[br]   = Sp   + (ll)BATCH * P * HKV;
        S16b[br] = S16p + (ll)BATCH * P * HKV;
        Usb[br]  = Usp  + (ll)BATCH * P * KVD;
        CXb[br]  = CXp  + (ll)BATCH * P * NTOK;
        Ob[br]   = out  + (ll)BATCH * NTOK * P;
    }

    auto fill = [](GemmDesc& g, const float* A, const float* B, float* C,
                   int M, int N, int K, int lda, int ldb, int ldc,
                   int aDiv, ll aS1, ll aS2, int bDiv, ll bS1, ll bS2,
                   int cDiv, ll cS1, ll cS2, float alpha,
                   int xB, int yB, int zB, int& cum) {
        g.A = A; g.B = B; g.C = C;
        g.M = M; g.N = N; g.K = K; g.lda = lda; g.ldb = ldb; g.ldc = ldc;
        g.aDiv = aDiv; g.aS1 = aS1; g.aS2 = aS2;
        g.bDiv = bDiv; g.bS1 = bS1; g.bS2 = bS2;
        g.cDiv = cDiv; g.cS1 = cS1; g.cS2 = cS2;
        g.alpha = alpha; g.xB = xB; g.yB = yB; g.off = cum;
        cum += xB * yB * zB;
    };

    Desc4 dG, dT, dS, dU, dCX, dO;
    dG.part = dT.part = dU.part = dCX.part = dO.part = nullptr;
    dS.part = partp;
    int nG = 0, nT = 0, nS = 0, nU = 0, nCX = 0, nO = 0;
    for (int br = 0; br < 4; br++) {
        const int Cb = Cb_[br], myt = myt_[br];

        // G[b][c][j] = sum_n emb[b][n][c] * emb_all[b][n][j]
        fill(dG.d[br], emb[br], emb_all, Gb[br],
             Cb, KVD, NTOK, Cb, KVD, KVD,
             1, (ll)NTOK * Cb, 0,  1, (ll)NTOK * KVD, 0,
             1, (ll)Cb * KVD, 0, 1.f, 8, myt, BATCH, nG);

        // T[b,h][c][j] = sum_d Wq[h][c][d] * G[b][d][j]
        fill(dT.d[br], Wq[br], Gb[br], Tb[br],
             Cb, KVD, Cb, Cb, KVD, KVD,
             NH, 0, (ll)Cb * Cb,  NH, (ll)Cb * KVD, 0,
             1, (ll)Cb * KVD, 0, 1.f, 8, myt, BATCH * NH, nT);

        // scores[b,h][c][o] = sum_k T[b,h][c][k] * Wk[h][o][k] / sqrt(960)  (+ stats)
        fill(dS.d[br], Tb[br], Wk, Sb[br],
             Cb, KVD, KVD, KVD, KVD, HKV,
             1, (ll)Cb * KVD, 0,  NH, 0, (ll)KVD * KVD,
             NH, (ll)Cb * HKV, KVD, rscale, 8, myt, BATCH * NH, nS);

        // Us[b][c][k] = 0.25 * sum_{ho} probs16[b][c][ho] * Wv_flat[ho][k]  (A = fp16)
        fill(dU.d[br], (const float*)S16b[br], Wv, Usb[br],
             Cb, KVD, HKV, HKV, KVD, KVD,
             1, (ll)Cb * HKV, 0,  1, 0, 0,
             1, (ll)Cb * KVD, 0, 0.25f, 8, myt, BATCH, nU);

        // ctx[b][c][n] = sum_k Us[b][c][k] * emb_all[b][n][k]
        fill(dCX.d[br], Usb[br], emb_all, CXb[br],
             Cb, NTOK, KVD, KVD, KVD, NTOK,
             1, (ll)Cb * KVD, 0,  1, (ll)NTOK * KVD, 0,
             1, (ll)Cb * NTOK, 0, 1.f, NTOK / 128, myt, BATCH, nCX);

        // O[b][n][j] = sum_c ctx[b][c][n] * Wo[j][c]
        fill(dO.d[br], CXb[br], Wo[br], Ob[br],
             NTOK, Cb, Cb, NTOK, Cb, Cb,
             1, (ll)Cb * NTOK, 0,  1, 0, 0,
             1, (ll)NTOK * Cb, 0, 1.f, myt, NTOK / 128, BATCH, nO);
    }

    // 8 launches
    tgemm_m<true,  true,  false, false><<<nG,  256>>>(dG);
    tgemm_m<false, true,  false, false><<<nT,  256>>>(dT);
    tgemm_m<false, false, true,  false><<<nS,  256>>>(dS);   // scores + fused stats
    mv_final_m<<<1, 128>>>(partp, mup, rsp);
    norm_softmax_m<<<30720, 256>>>(Sp, S16p, mup, rsp);
    tgemm_m<false, true,  false, true ><<<nU,  256>>>(dU);   // fp16-A probs GEMM
    tgemm_m<false, false, false, false><<<nCX, 256>>>(dCX);
    tgemm_m<true,  false, false, false><<<nO,  256>>>(dO);

    (void)in_sizes; (void)n_in; (void)out_size;
}

// round 9
// speedup vs baseline: 6.1239x; 1.0008x over previous
#include <cuda_runtime.h>
#include <cuda_fp16.h>
#include <cstdint>
#include <math.h>

#define BATCH 8
#define NTOK  1024
#define KVD   960
#define NH    4
#define HKV   (NH * KVD)   // 3840
#define CT    960          // sum of branch channels 64+128+256+512

typedef long long ll;

#define BR_C(br)   (64 << (br))
#define BR_P(br)   ((64 << (br)) - 64)

// ---------------- scratch (static __device__ — no allocations allowed) ----------------
static __device__ __half g_G  [(size_t)BATCH * CT * KVD];
static __device__ __half g_T  [(size_t)BATCH * NH * CT * KVD];
static __device__ float  g_S  [(size_t)BATCH * CT * HKV];      // fp32 scores (stats+softmax)
static __device__ __half g_S16[(size_t)BATCH * CT * HKV];      // fp16 probs
static __device__ __half g_Us [(size_t)BATCH * CT * KVD];
static __device__ __half g_CX [(size_t)BATCH * CT * NTOK];
static __device__ float  g_mu [4 * BATCH * NH];
static __device__ float  g_rs [4 * BATCH * NH];
static __device__ float  g_part[2048 * 2];

// ---------------- fp16 helpers ----------------
__device__ __forceinline__ uint32_t h2pack(float lo, float hi) {
    uint32_t r;
    asm("cvt.rn.f16x2.f32 %0, %1, %2;" : "=r"(r) : "f"(hi), "f"(lo));
    return r;
}
__device__ __forceinline__ uint32_t packh(__half lo, __half hi) {
    __half2 h = __halves2half2(lo, hi);
    return *(uint32_t*)&h;
}

__device__ __forceinline__ void mma16816(float* c, const uint4& a, const uint2& b) {
    asm volatile(
        "mma.sync.aligned.m16n8k16.row.col.f32.f16.f16.f32 "
        "{%0,%1,%2,%3}, {%4,%5,%6,%7}, {%8,%9}, {%0,%1,%2,%3};"
        : "+f"(c[0]), "+f"(c[1]), "+f"(c[2]), "+f"(c[3])
        : "r"(a.x), "r"(a.y), "r"(a.z), "r"(a.w), "r"(b.x), "r"(b.y));
}

// ======================= fp32 producers (proven round-6 code) =======================
template <bool T>
__device__ __forceinline__ void ldgA(const float* __restrict__ A, int lda, int tileM,
                                     int M, int kt, int t, float4* q)
{
    const int b = t >> 4, kb = b >> 3, mb = b & 7;
    const int m0 = tileM + mb * 16 + ((t & 15) >> 1);
    const int k0 = kt + kb * 16 + (t & 1) * 4;
    const bool v0 = m0 < M, v1 = (m0 + 8) < M;
    if (!T) {
        const float4 Z = make_float4(0.f, 0.f, 0.f, 0.f);
        q[0] = v0 ? *(const float4*)(A + (ll)m0 * lda + k0)           : Z;
        q[1] = v0 ? *(const float4*)(A + (ll)m0 * lda + k0 + 8)       : Z;
        q[2] = v1 ? *(const float4*)(A + (ll)(m0 + 8) * lda + k0)     : Z;
        q[3] = v1 ? *(const float4*)(A + (ll)(m0 + 8) * lda + k0 + 8) : Z;
    } else {
        float* f = (float*)q;
#pragma unroll
        for (int run = 0; run < 2; run++)
#pragma unroll
            for (int i = 0; i < 4; i++) {
                const ll ko = (ll)(k0 + run * 8 + i) * lda;
                f[run * 4 + i]     = v0 ? A[ko + m0]     : 0.f;
                f[8 + run * 4 + i] = v1 ? A[ko + m0 + 8] : 0.f;
            }
    }
}

__device__ __forceinline__ void stsA(uint4* sA, int t, const float4* q)
{
    uint4 v0, v1;
    v0.x = h2pack(q[0].x, q[0].y); v0.y = h2pack(q[2].x, q[2].y);
    v0.z = h2pack(q[1].x, q[1].y); v0.w = h2pack(q[3].x, q[3].y);
    v1.x = h2pack(q[0].z, q[0].w); v1.y = h2pack(q[2].z, q[2].w);
    v1.z = h2pack(q[1].z, q[1].w); v1.w = h2pack(q[3].z, q[3].w);
    const int b = t >> 4;
    const int l0 = (t & 15) * 2, l1 = l0 + 1;
    sA[b * 32 + (l0 ^ ((l0 >> 3) & 1))] = v0;
    sA[b * 32 + (l1 ^ ((l1 >> 3) & 1))] = v1;
}

template <bool T>
__device__ __forceinline__ void ldgB(const float* __restrict__ B, int ldb, int tileN,
                                     int N, int kt, int t, float4* q)
{
    const int b = t >> 3, kb = b >> 4, nb = b & 15;
    const int n = tileN + nb * 8 + (t & 7);
    const int k0 = kt + kb * 16;
    const bool v = n < N;
    if (!T) {
        const float4 Z = make_float4(0.f, 0.f, 0.f, 0.f);
        const float4* p = (const float4*)(B + (ll)n * ldb + k0);
        q[0] = v ? p[0] : Z; q[1] = v ? p[1] : Z;
        q[2] = v ? p[2] : Z; q[3] = v ? p[3] : Z;
    } else {
        float* f = (float*)q;
#pragma unroll
        for (int i = 0; i < 16; i++)
            f[i] = v ? B[(ll)(k0 + i) * ldb + n] : 0.f;
    }
}

__device__ __forceinline__ void stsB(uint4* sB, int t, const float4* q)
{
    uint4 v0, v1;
    v0.x = h2pack(q[0].x, q[0].y); v0.y = h2pack(q[2].x, q[2].y);
    v0.z = h2pack(q[0].z, q[0].w); v0.w = h2pack(q[2].z, q[2].w);
    v1.x = h2pack(q[1].x, q[1].y); v1.y = h2pack(q[3].x, q[3].y);
    v1.z = h2pack(q[1].z, q[1].w); v1.w = h2pack(q[3].z, q[3].w);
    const int b = t >> 3;
    const int u0 = (t & 7) * 2, u1 = u0 + 1;
    sB[b * 16 + (u0 ^ ((u0 >> 3) & 1))] = v0;
    sB[b * 16 + (u1 ^ ((u1 >> 3) & 1))] = v1;
}

// ======================= fp16 producers (pure repack, zero conversion) =======================
// A fp16 row-major
__device__ __forceinline__ void ldgA16(const __half* __restrict__ A, int lda, int tileM,
                                       int M, int kt, int t, uint2* w)
{
    const int b = t >> 4, kb = b >> 3, mb = b & 7;
    const int m0 = tileM + mb * 16 + ((t & 15) >> 1);
    const int k0 = kt + kb * 16 + (t & 1) * 4;
    const bool v0 = m0 < M, v1 = (m0 + 8) < M;
    const uint2 Z = make_uint2(0u, 0u);
    w[0] = v0 ? *(const uint2*)(A + (ll)m0 * lda + k0)           : Z;   // m0  k0..3
    w[1] = v0 ? *(const uint2*)(A + (ll)m0 * lda + k0 + 8)       : Z;   // m0  k8..11
    w[2] = v1 ? *(const uint2*)(A + (ll)(m0 + 8) * lda + k0)     : Z;   // m1  k0..3
    w[3] = v1 ? *(const uint2*)(A + (ll)(m0 + 8) * lda + k0 + 8) : Z;   // m1  k8..11
}

// A fp16 k-major (transposed)
__device__ __forceinline__ void ldgA16T(const __half* __restrict__ A, int lda, int tileM,
                                        int M, int kt, int t, uint2* w)
{
    const int b = t >> 4, kb = b >> 3, mb = b & 7;
    const int m0 = tileM + mb * 16 + ((t & 15) >> 1);
    const int k0 = kt + kb * 16 + (t & 1) * 4;
    const bool v0 = m0 < M, v1 = (m0 + 8) < M;
    const __half Z = __float2half(0.f);
    __half h0[8], h1[8];
#pragma unroll
    for (int run = 0; run < 2; run++)
#pragma unroll
        for (int i = 0; i < 4; i++) {
            const ll ko = (ll)(k0 + run * 8 + i) * lda;
            h0[run * 4 + i] = v0 ? A[ko + m0]     : Z;
            h1[run * 4 + i] = v1 ? A[ko + m0 + 8] : Z;
        }
    w[0] = make_uint2(packh(h0[0], h0[1]), packh(h0[2], h0[3]));   // m0 k0..3
    w[1] = make_uint2(packh(h0[4], h0[5]), packh(h0[6], h0[7]));   // m0 k8..11
    w[2] = make_uint2(packh(h1[0], h1[1]), packh(h1[2], h1[3]));   // m1 k0..3
    w[3] = make_uint2(packh(h1[4], h1[5]), packh(h1[6], h1[7]));   // m1 k8..11
}

__device__ __forceinline__ void stsA16(uint4* sA, int t, const uint2* w)
{
    uint4 v0, v1;
    v0.x = w[0].x; v0.y = w[2].x; v0.z = w[1].x; v0.w = w[3].x;
    v1.x = w[0].y; v1.y = w[2].y; v1.z = w[1].y; v1.w = w[3].y;
    const int b = t >> 4;
    const int l0 = (t & 15) * 2, l1 = l0 + 1;
    sA[b * 32 + (l0 ^ ((l0 >> 3) & 1))] = v0;
    sA[b * 32 + (l1 ^ ((l1 >> 3) & 1))] = v1;
}

// B fp16 k-major (transposed): build swizzled uint4 pair directly
__device__ __forceinline__ void ldgB16T(const __half* __restrict__ B, int ldb, int tileN,
                                        int N, int kt, int t, uint4& v0, uint4& v1)
{
    const int b = t >> 3, kb = b >> 4, nb = b & 15;
    const int n = tileN + nb * 8 + (t & 7);
    const int k0 = kt + kb * 16;
    const bool v = n < N;
    const __half Z = __float2half(0.f);
    __half f[16];
#pragma unroll
    for (int i = 0; i < 16; i++)
        f[i] = v ? B[(ll)(k0 + i) * ldb + n] : Z;
    v0.x = packh(f[0],  f[1]);  v0.y = packh(f[8],  f[9]);
    v0.z = packh(f[2],  f[3]);  v0.w = packh(f[10], f[11]);
    v1.x = packh(f[4],  f[5]);  v1.y = packh(f[12], f[13]);
    v1.z = packh(f[6],  f[7]);  v1.w = packh(f[14], f[15]);
}

__device__ __forceinline__ void stsB16(uint4* sB, int t, const uint4& v0, const uint4& v1)
{
    const int b = t >> 3;
    const int u0 = (t & 7) * 2, u1 = u0 + 1;
    sB[b * 16 + (u0 ^ ((u0 >> 3) & 1))] = v0;
    sB[b * 16 + (u1 ^ ((u1 >> 3) & 1))] = v1;
}

// ======================= merged-stage GEMM descriptors =======================
struct GemmDesc {
    const float* A;
    const float* B;
    float*       C;
    int M, N, K, lda, ldb, ldc;
    int aDiv, bDiv, cDiv;
    ll aS1, aS2, bS1, bS2, cS1, cS2;
    float alpha;
    int xB, yB;
    int off;
};
struct Desc4 { GemmDesc d[4]; float* part; };

// ======================= fp16 tensor-core merged batched GEMM =======================
// AH/BH: operand stored fp16. CH: C written fp16. STATS: fused (sum,sumsq) per tile.
template <bool TA, bool TB, bool STATS, bool AH, bool BH, bool CH>
__global__ __launch_bounds__(256, 2)
void tgemm_m(Desc4 ds)
{
    __shared__ uint4 sA[2][512];
    __shared__ uint4 sB[2][512];

    const int bid = blockIdx.x;
    int br = 0;
    if (bid >= ds.d[1].off) br = 1;
    if (bid >= ds.d[2].off) br = 2;
    if (bid >= ds.d[3].off) br = 3;
    const GemmDesc& g = ds.d[br];

    const int local = bid - g.off;
    const int x  = local % g.xB;
    const int t2 = local / g.xB;
    const int y  = t2 % g.yB;
    const int z  = t2 / g.yB;

    const ll aOff = (ll)(z / g.aDiv) * g.aS1 + (ll)(z % g.aDiv) * g.aS2;
    const ll bOff = (ll)(z / g.bDiv) * g.bS1 + (ll)(z % g.bDiv) * g.bS2;
    const ll cOff = (ll)(z / g.cDiv) * g.cS1 + (ll)(z % g.cDiv) * g.cS2;
    const float*  A   = g.A + aOff;
    const __half* A16 = (const __half*)g.A + aOff;
    const float*  B   = g.B + bOff;
    const __half* B16 = (const __half*)g.B + bOff;
    float*        C   = g.C + cOff;
    __half*       C16 = (__half*)g.C + cOff;
    const int M = g.M, N = g.N, K = g.K;
    const int lda = g.lda, ldb = g.ldb, ldc = g.ldc;
    const float alpha = g.alpha;

    const int tid  = threadIdx.x;
    const int lane = tid & 31;
    const int wid  = tid >> 5;
    const int wm   = wid >> 1;
    const int wn   = wid & 1;
    const int tileM = y * 128;
    const int tileN = x * 128;

    float acc[2][8][4];
#pragma unroll
    for (int i = 0; i < 2; i++)
#pragma unroll
        for (int j = 0; j < 8; j++)
#pragma unroll
            for (int t = 0; t < 4; t++) acc[i][j][t] = 0.f;

    const int la  = lane ^ ((lane >> 3) & 1);
    const int lb2 = (((lane >> 1) ^ ((lane >> 4) & 1)) << 1) | (lane & 1);

    auto compute = [&](int buf) {
        const uint4* ap = sA[buf];
        const uint2* bp = (const uint2*)sB[buf];
#pragma unroll
        for (int s = 0; s < 2; s++) {
            uint4 av[2];
#pragma unroll
            for (int i = 0; i < 2; i++)
                av[i] = ap[(s * 8 + wm * 2 + i) * 32 + la];
            uint2 bv[8];
#pragma unroll
            for (int j = 0; j < 8; j++)
                bv[j] = bp[(s * 16 + wn * 8 + j) * 32 + lb2];
#pragma unroll
            for (int i = 0; i < 2; i++)
#pragma unroll
                for (int j = 0; j < 8; j++)
                    mma16816(acc[i][j], av[i], bv[j]);
        }
    };

    const int nk = K >> 5;
    float4 qa[4], qb[4];
    uint2  wa[4];
    uint4  wb0, wb1;

    auto produceA = [&](int kt) {
        if (AH) { if (TA) ldgA16T(A16, lda, tileM, M, kt, tid, wa);
                  else    ldgA16 (A16, lda, tileM, M, kt, tid, wa); }
        else      ldgA<TA>(A, lda, tileM, M, kt, tid, qa);
    };
    auto produceB = [&](int kt) {
        if (BH) ldgB16T(B16, ldb, tileN, N, kt, tid, wb0, wb1);
        else    ldgB<TB>(B, ldb, tileN, N, kt, tid, qb);
    };
    auto storeAB = [&](int buf) {
        if (AH) stsA16(sA[buf], tid, wa); else stsA(sA[buf], tid, qa);
        if (BH) stsB16(sB[buf], tid, wb0, wb1); else stsB(sB[buf], tid, qb);
    };

    produceA(0);
    produceB(0);
    storeAB(0);
    __syncthreads();

    int buf = 0;
    for (int it = 1; it < nk; it++) {
        produceA(it * 32);
        produceB(it * 32);
        compute(buf);
        storeAB(buf ^ 1);
        __syncthreads();
        buf ^= 1;
    }
    compute(buf);

    if (STATS) {
        float s = 0.f, s2 = 0.f;
#pragma unroll
        for (int i = 0; i < 2; i++)
#pragma unroll
            for (int j = 0; j < 8; j++)
#pragma unroll
                for (int t = 0; t < 4; t++) {
                    const float v = acc[i][j][t] * alpha;
                    s += v;
                    s2 += v * v;
                }
        __syncthreads();
        float* sa = (float*)&sA[0][0];
        float* sb = sa + 256;
        sa[tid] = s; sb[tid] = s2;
        __syncthreads();
        for (int off = 128; off > 0; off >>= 1) {
            if (tid < off) { sa[tid] += sa[tid + off]; sb[tid] += sb[tid + off]; }
            __syncthreads();
        }
        if (tid == 0) {
            ds.part[bid * 2 + 0] = sa[0];
            ds.part[bid * 2 + 1] = sb[0];
        }
    }

#pragma unroll
    for (int i = 0; i < 2; i++) {
#pragma unroll
        for (int j = 0; j < 8; j++) {
            const int row = tileM + wm * 32 + i * 16 + (lane >> 2);
            const int col = tileN + wn * 64 + j * 8 + ((lane & 3) << 1);
            if (col < N) {
                if (CH) {
                    if (row < M)
                        *(uint32_t*)&C16[(ll)row * ldc + col] =
                            h2pack(acc[i][j][0] * alpha, acc[i][j][1] * alpha);
                    if (row + 8 < M)
                        *(uint32_t*)&C16[(ll)(row + 8) * ldc + col] =
                            h2pack(acc[i][j][2] * alpha, acc[i][j][3] * alpha);
                } else {
                    if (row < M) {
                        float2 v = make_float2(acc[i][j][0] * alpha, acc[i][j][1] * alpha);
                        *(float2*)&C[(ll)row * ldc + col] = v;
                    }
                    if (row + 8 < M) {
                        float2 v = make_float2(acc[i][j][2] * alpha, acc[i][j][3] * alpha);
                        *(float2*)&C[(ll)(row + 8) * ldc + col] = v;
                    }
                }
            }
        }
    }
}

// ---------------- final stats: fold per-tile partials -> mu, rs ---------------------------
__global__ void mv_final_m(const float* __restrict__ part,
                           float* __restrict__ mu, float* __restrict__ rs)
{
    const int t = threadIdx.x;
    if (t >= 128) return;
    const int br = t >> 5, z = t & 31;
    const int offs[4] = {0, 256, 512, 1024};
    const int cnt[4]  = {8, 8, 16, 32};
    const int base = offs[br] + z * cnt[br];
    float s = 0.f, s2 = 0.f;
    for (int i = 0; i < cnt[br]; i++) {
        s  += part[(base + i) * 2 + 0];
        s2 += part[(base + i) * 2 + 1];
    }
    const float cntf = (float)BR_C(br) * (float)KVD;
    const float m = s / cntf;
    const float var = s2 / cntf - m * m;
    mu[t] = m;
    rs[t] = rsqrtf(var + 1e-5f);
}

// ---------------- fused norm + softmax: fp32 scores -> fp16 probs ------------------------
__global__ __launch_bounds__(256) void norm_softmax_m(
    const float* __restrict__ S, __half* __restrict__ S16,
    const float* __restrict__ mu, const float* __restrict__ rs)
{
    const int gid = blockIdx.x;
    int br = 0;
    if (gid >= 2048)  br = 1;
    if (gid >= 6144)  br = 2;
    if (gid >= 14336) br = 3;
    const int off = (2048 << br) - 2048;
    const int local = gid - off;
    const int C = BR_C(br);

    const int h = local % NH;
    const int bc = local / NH;
    const int c = bc % C;
    const int b = bc / C;
    const ll eoff = (ll)BATCH * BR_P(br) * HKV + ((ll)b * C + c) * HKV + (ll)h * KVD;
    const float4* row4  = (const float4*)(S + eoff);
    uint2*        row16 = (uint2*)(S16 + eoff);
    const float m = mu[br * 32 + b * NH + h];
    const float r = rs[br * 32 + b * NH + h];

    const int tid = threadIdx.x;
    float4 e = make_float4(0.f, 0.f, 0.f, 0.f);
    float lsum = 0.f;
    if (tid < 240) {
        const float4 v = row4[tid];
        e.x = __expf((v.x - m) * r);
        e.y = __expf((v.y - m) * r);
        e.z = __expf((v.z - m) * r);
        e.w = __expf((v.w - m) * r);
        lsum = (e.x + e.y) + (e.z + e.w);
    }
    __shared__ float red[256];
    red[tid] = lsum;
    __syncthreads();
    for (int o = 128; o > 0; o >>= 1) {
        if (tid < o) red[tid] += red[tid + o];
        __syncthreads();
    }
    const float inv = 1.f / red[0];
    if (tid < 240) {
        uint2 o16;
        o16.x = h2pack(e.x * inv, e.y * inv);
        o16.y = h2pack(e.z * inv, e.w * inv);
        row16[tid] = o16;
    }
}

// ---------------- host launch ------------------------------------------------------------
extern "C" void kernel_launch(void* const* d_in, const int* in_sizes, int n_in,
                              void* d_out, int out_size)
{
    const float* emb[4]  = {(const float*)d_in[0], (const float*)d_in[1],
                            (const float*)d_in[2], (const float*)d_in[3]};
    const float* emb_all = (const float*)d_in[4];
    const float* Wq[4]   = {(const float*)d_in[5], (const float*)d_in[6],
                            (const float*)d_in[7], (const float*)d_in[8]};
    const float* Wk      = (const float*)d_in[9];
    const float* Wv      = (const float*)d_in[10];
    const float* Wo[4]   = {(const float*)d_in[11], (const float*)d_in[12],
                            (const float*)d_in[13], (const float*)d_in[14]};
    float* out = (float*)d_out;

    float *Sp, *mup, *rsp, *partp;
    __half *Gp, *Tp, *S16p, *Usp, *CXp;
    cudaGetSymbolAddress((void**)&Gp,    g_G);
    cudaGetSymbolAddress((void**)&Tp,    g_T);
    cudaGetSymbolAddress((void**)&Sp,    g_S);
    cudaGetSymbolAddress((void**)&S16p,  g_S16);
    cudaGetSymbolAddress((void**)&Usp,   g_Us);
    cudaGetSymbolAddress((void**)&CXp,   g_CX);
    cudaGetSymbolAddress((void**)&mup,   g_mu);
    cudaGetSymbolAddress((void**)&rsp,   g_rs);
    cudaGetSymbolAddress((void**)&partp, g_part);

    const float rscale = 1.f / sqrtf(960.f);

    float* Sb[4];
    float* Ob[4];
    __half *Gb[4], *Tb[4], *S16b[4], *Usb[4], *CXb[4];
    int Cb_[4], myt_[4];
    for (int br = 0; br < 4; br++) {
        const int Cb = BR_C(br), P = BR_P(br);
        Cb_[br] = Cb;
        myt_[br] = (Cb + 127) / 128;
        Gb[br]   = Gp   + (ll)BATCH * P * KVD;
        Tb[br]   = Tp   + (ll)BATCH * NH * P * KVD;
        Sb[br]   = Sp   + (ll)BATCH * P * HKV;
        S16b[br] = S16p + (ll)BATCH * P * HKV;
        Usb[br]  = Usp  + (ll)BATCH * P * KVD;
        CXb[br]  = CXp  + (ll)BATCH * P * NTOK;
        Ob[br]   = out  + (ll)BATCH * NTOK * P;
    }

    auto fill = [](GemmDesc& g, const void* A, const void* B, void* C,
                   int M, int N, int K, int lda, int ldb, int ldc,
                   int aDiv, ll aS1, ll aS2, int bDiv, ll bS1, ll bS2,
                   int cDiv, ll cS1, ll cS2, float alpha,
                   int xB, int yB, int zB, int& cum) {
        g.A = (const float*)A; g.B = (const float*)B; g.C = (float*)C;
        g.M = M; g.N = N; g.K = K; g.lda = lda; g.ldb = ldb; g.ldc = ldc;
        g.aDiv = aDiv; g.aS1 = aS1; g.aS2 = aS2;
        g.bDiv = bDiv; g.bS1 = bS1; g.bS2 = bS2;
        g.cDiv = cDiv; g.cS1 = cS1; g.cS2 = cS2;
        g.alpha = alpha; g.xB = xB; g.yB = yB; g.off = cum;
        cum += xB * yB * zB;
    };

    Desc4 dG, dT, dS, dU, dCX, dO;
    dG.part = dT.part = dU.part = dCX.part = dO.part = nullptr;
    dS.part = partp;
    int nG = 0, nT = 0, nS = 0, nU = 0, nCX = 0, nO = 0;
    for (int br = 0; br < 4; br++) {
        const int Cb = Cb_[br], myt = myt_[br];

        // G[b][c][j] = sum_n emb[b][n][c] * emb_all[b][n][j]      -> fp16 C
        fill(dG.d[br], emb[br], emb_all, Gb[br],
             Cb, KVD, NTOK, Cb, KVD, KVD,
             1, (ll)NTOK * Cb, 0,  1, (ll)NTOK * KVD, 0,
             1, (ll)Cb * KVD, 0, 1.f, 8, myt, BATCH, nG);

        // T[b,h][c][j] = sum_d Wq[h][c][d] * G16[b][d][j]          -> fp16 B, fp16 C
        fill(dT.d[br], Wq[br], Gb[br], Tb[br],
             Cb, KVD, Cb, Cb, KVD, KVD,
             NH, 0, (ll)Cb * Cb,  NH, (ll)Cb * KVD, 0,
             1, (ll)Cb * KVD, 0, 1.f, 8, myt, BATCH * NH, nT);

        // scores[b,h][c][o] = sum_k T16[b,h][c][k] * Wk[h][o][k]   -> fp16 A, fp32 C + stats
        fill(dS.d[br], Tb[br], Wk, Sb[br],
             Cb, KVD, KVD, KVD, KVD, HKV,
             1, (ll)Cb * KVD, 0,  NH, 0, (ll)KVD * KVD,
             NH, (ll)Cb * HKV, KVD, rscale, 8, myt, BATCH * NH, nS);

        // Us[b][c][k] = 0.25 * sum_{ho} probs16[b][c][ho] * Wv[ho][k]  -> fp16 A, fp16 C
        fill(dU.d[br], S16b[br], Wv, Usb[br],
             Cb, KVD, HKV, HKV, KVD, KVD,
             1, (ll)Cb * HKV, 0,  1, 0, 0,
             1, (ll)Cb * KVD, 0, 0.25f, 8, myt, BATCH, nU);

        // ctx[b][c][n] = sum_k Us16[b][c][k] * emb_all[b][n][k]    -> fp16 A, fp16 C
        fill(dCX.d[br], Usb[br], emb_all, CXb[br],
             Cb, NTOK, KVD, KVD, KVD, NTOK,
             1, (ll)Cb * KVD, 0,  1, (ll)NTOK * KVD, 0,
             1, (ll)Cb * NTOK, 0, 1.f, NTOK / 128, myt, BATCH, nCX);

        // O[b][n][j] = sum_c ctx16[b][c][n] * Wo[j][c]             -> fp16 A (T), fp32 C
        fill(dO.d[br], CXb[br], Wo[br], Ob[br],
             NTOK, Cb, Cb, NTOK, Cb, Cb,
             1, (ll)Cb * NTOK, 0,  1, 0, 0,
             1, (ll)NTOK * Cb, 0, 1.f, myt, NTOK / 128, BATCH, nO);
    }

    // 8 launches                    TA     TB     STATS  AH     BH     CH
    tgemm_m<true,  true,  false, false, false, true ><<<nG,  256>>>(dG);
    tgemm_m<false, true,  false, false, true,  true ><<<nT,  256>>>(dT);
    tgemm_m<false, false, true,  true,  false, false><<<nS,  256>>>(dS);
    mv_final_m<<<1, 128>>>(partp, mup, rsp);
    norm_softmax_m<<<30720, 256>>>(Sp, S16p, mup, rsp);
    tgemm_m<false, true,  false, true,  false, true ><<<nU,  256>>>(dU);
    tgemm_m<false, false, false, true,  false, true ><<<nCX, 256>>>(dCX);
    tgemm_m<true,  false, false, true,  false, false><<<nO,  256>>>(dO);

    (void)in_sizes; (void)n_in; (void)out_size;
}